// round 9
// baseline (speedup 1.0000x reference)
#include <cuda_runtime.h>
#include <cuda_fp16.h>
#include <math.h>
#include <cstdint>

// ---------------- problem constants ----------------
#define TOK    100352          // 32 * 56 * 56 tokens
#define CC     256
#define HEADS  8
#define HD     32
#define WS     7
#define NWIN   49
#define MLPD   1024
#define HH     56
#define WW     56
#define SSH    3
#define NWB    64
#define NWTOT  2048
#define ATT_SCALE 0.17677669529663687f
#define LN_EPS 1e-5f

// ---------------- scratch (static device globals; no allocation) ----------------
__device__ __half g_qkv [(size_t)TOK * 3 * CC];
__device__ __half g_att [(size_t)TOK * CC];
__device__ float  g_x1  [(size_t)TOK * CC];
__device__ __half g_h   [(size_t)TOK * MLPD];
__device__ float2 g_st1[TOK];
__device__ float2 g_st2[TOK];
// transposed weights [N,K] row-major, fp16
__device__ __half g_wq [768 * 256];
__device__ __half g_wp [256 * 256];
__device__ __half g_w1 [1024 * 256];
__device__ __half g_w2 [256 * 1024];

// ---------------- helpers ----------------
__device__ __forceinline__ uint32_t smem_u32(const void* p) {
    uint32_t a;
    asm("{ .reg .u64 t; cvta.to.shared.u64 t, %1; cvt.u32.u64 %0, t; }" : "=r"(a) : "l"(p));
    return a;
}
__device__ __forceinline__ void cp_async16(uint32_t dst, const void* src) {
    asm volatile("cp.async.cg.shared.global [%0], [%1], 16;" :: "r"(dst), "l"(src));
}
#define CP_COMMIT() asm volatile("cp.async.commit_group;" ::: "memory")

// m16n8k16 fp16 MMA, fp32 accumulate
__device__ __forceinline__ void mma_f16(float* c,
                                        uint32_t a0, uint32_t a1, uint32_t a2, uint32_t a3,
                                        uint32_t b0, uint32_t b1) {
    asm volatile(
        "mma.sync.aligned.m16n8k16.row.col.f32.f16.f16.f32 "
        "{%0,%1,%2,%3}, {%4,%5,%6,%7}, {%8,%9}, {%0,%1,%2,%3};"
        : "+f"(c[0]), "+f"(c[1]), "+f"(c[2]), "+f"(c[3])
        : "r"(a0), "r"(a1), "r"(a2), "r"(a3), "r"(b0), "r"(b1));
}

// scalar-LDS K-step MMA over CH-half chunk with row stride LDX (round-7 proven form)
template<int LDX, int CH>
__device__ __forceinline__ void chunk_mma(const __half* As, const __half* Bs,
                                          int wm, int wn, int g, int t4,
                                          float acc[4][4][4]) {
    #pragma unroll
    for (int ks = 0; ks < CH / 16; ks++) {
        const int kb = ks * 16;
        uint32_t bf[4][2];
        #pragma unroll
        for (int ni = 0; ni < 4; ni++) {
            const __half* bp = Bs + (wn + ni * 8 + g) * LDX + kb + t4 * 2;
            bf[ni][0] = *reinterpret_cast<const uint32_t*>(bp);
            bf[ni][1] = *reinterpret_cast<const uint32_t*>(bp + 8);
        }
        #pragma unroll
        for (int mi = 0; mi < 4; mi++) {
            const __half* ap = As + (wm + mi * 16 + g) * LDX + kb + t4 * 2;
            uint32_t a0 = *reinterpret_cast<const uint32_t*>(ap);
            uint32_t a1 = *reinterpret_cast<const uint32_t*>(ap + 8 * LDX);
            uint32_t a2 = *reinterpret_cast<const uint32_t*>(ap + 8);
            uint32_t a3 = *reinterpret_cast<const uint32_t*>(ap + 8 * LDX + 8);
            #pragma unroll
            for (int ni = 0; ni < 4; ni++)
                mma_f16(acc[mi][ni], a0, a1, a2, a3, bf[ni][0], bf[ni][1]);
        }
    }
}

// shared epilogue. MODE 0: half out (QKV)  MODE 1: float res+scatter (proj)
// MODE 2: half gelu out (MLP1)  MODE 3: float res out (MLP2)
template<int MODE, int NDIM>
__device__ __forceinline__ void gemm_epilogue(float acc[4][4][4],
                                              int m0, int n0, int wm, int wn, int g, int t4,
                                              const float* __restrict__ bias,
                                              void* __restrict__ OutV,
                                              const float* __restrict__ res) {
    #pragma unroll
    for (int mi = 0; mi < 4; mi++) {
        #pragma unroll
        for (int h = 0; h < 2; h++) {
            int m = m0 + wm + mi * 16 + g + h * 8;
            size_t drow;
            if (MODE == 1) {
                int w = m / NWIN, ntok = m % NWIN;
                int bb2 = w / NWB, wi = w % NWB;
                int wy = wi >> 3, wx = wi & 7;
                int hy = wy * WS + ntok / WS, hx = wx * WS + ntok % WS;
                int oy = (hy + SSH) % HH, ox = (hx + SSH) % WW;
                drow = ((size_t)bb2 * HH * WW + oy * WW + ox) * CC;
            } else {
                drow = (size_t)m * NDIM;
            }
            #pragma unroll
            for (int ni = 0; ni < 4; ni++) {
                int n = n0 + wn + ni * 8 + 2 * t4;
                float2 bv = *reinterpret_cast<const float2*>(bias + n);
                float vx = acc[mi][ni][2 * h + 0] + bv.x;
                float vy = acc[mi][ni][2 * h + 1] + bv.y;
                if (MODE == 1 || MODE == 3) {
                    float2 r = *reinterpret_cast<const float2*>(res + drow + n);
                    float2 o = { vx + r.x, vy + r.y };
                    *reinterpret_cast<float2*>((float*)OutV + drow + n) = o;
                } else {
                    if (MODE == 2) {
                        vx = 0.5f * vx * (1.0f + erff(vx * 0.70710678118654752f));
                        vy = 0.5f * vy * (1.0f + erff(vy * 0.70710678118654752f));
                    }
                    *reinterpret_cast<__half2*>((__half*)OutV + drow + n) =
                        __floats2half2_rn(vx, vy);
                }
            }
        }
    }
}

// ---------------- cp.async fp16 GEMM, 64-half K chunks: proj / MLP2 ----------------
#define LDKH2 72
template<int MODE, int KDIM, int NDIM>
__global__ __launch_bounds__(256)
void mma_gemm(const __half* __restrict__ A, const __half* __restrict__ Wt,
              const float* __restrict__ bias, void* __restrict__ Out,
              const float* __restrict__ res)
{
    extern __shared__ char smraw[];
    __half* sm = reinterpret_cast<__half*>(smraw);
    const uint32_t sbase = smem_u32(smraw);

    const int tid  = threadIdx.x;
    const int wid  = tid >> 5, lane = tid & 31;
    const int g    = lane >> 2, t4 = lane & 3;
    const int wm   = (wid & 1) * 64;
    const int wn   = (wid >> 1) * 32;
    const int m0   = blockIdx.y * 128;
    const int n0   = blockIdx.x * 128;

    constexpr int NC = KDIM / 64;
    constexpr int STAGE = 2 * 128 * LDKH2;

    auto load_chunk = [&](int c, int s) {
        const int k0 = c * 64;
        uint32_t sa  = sbase + (uint32_t)(s * STAGE) * 2u;
        uint32_t sb2 = sa + 128u * LDKH2 * 2u;
        #pragma unroll
        for (int t = 0; t < 4; t++) {
            int f = t * 256 + tid;
            int row = f >> 3, seg = f & 7;
            cp_async16(sa  + (uint32_t)(row * LDKH2) * 2u + seg * 16,
                       A  + (size_t)(m0 + row) * KDIM + k0 + seg * 8);
            cp_async16(sb2 + (uint32_t)(row * LDKH2) * 2u + seg * 16,
                       Wt + (size_t)(n0 + row) * KDIM + k0 + seg * 8);
        }
        CP_COMMIT();
    };

    float acc[4][4][4];
    #pragma unroll
    for (int i = 0; i < 4; i++)
        #pragma unroll
        for (int j = 0; j < 4; j++)
            #pragma unroll
            for (int e = 0; e < 4; e++) acc[i][j][e] = 0.0f;

    load_chunk(0, 0);
    if (NC > 1) load_chunk(1, 1);

    for (int c = 0; c < NC; c++) {
        if (c + 1 < NC) asm volatile("cp.async.wait_group 1;" ::: "memory");
        else            asm volatile("cp.async.wait_group 0;" ::: "memory");
        __syncthreads();
        const __half* As = sm + (c & 1) * STAGE;
        const __half* Bs = As + 128 * LDKH2;
        chunk_mma<LDKH2, 64>(As, Bs, wm, wn, g, t4, acc);
        if (c + 2 < NC) {
            __syncthreads();
            load_chunk(c + 2, c & 1);
        }
    }
    gemm_epilogue<MODE, NDIM>(acc, m0, n0, wm, wn, g, t4, bias, Out, res);
}

// ---------------- LN-fused fp16 GEMM (32-half chunks): QKV / MLP1 ----------------
#define LDKH 40
template<int MODE, int LNMODE, int KDIM, int NDIM>
__global__ __launch_bounds__(256)
void mma_gemm_ln(const float* __restrict__ X, const __half* __restrict__ Wt,
                 const float2* __restrict__ stats,
                 const float* __restrict__ lng, const float* __restrict__ lnb,
                 const float* __restrict__ bias, void* __restrict__ Out)
{
    extern __shared__ char smraw[];
    __half* sm = reinterpret_cast<__half*>(smraw);
    constexpr int STAGE = 2 * 128 * LDKH;
    float* gS = reinterpret_cast<float*>(smraw + 2 * STAGE * 2);
    float* bS = gS + KDIM;

    const int tid  = threadIdx.x;
    const int wid  = tid >> 5, lane = tid & 31;
    const int g    = lane >> 2, t4 = lane & 3;
    const int wm   = (wid & 1) * 64;
    const int wn   = (wid >> 1) * 32;
    const int m0   = blockIdx.y * 128;
    const int n0   = blockIdx.x * 128;

    constexpr int NC = KDIM / 32;

    if (tid < KDIM) { gS[tid] = lng[tid]; bS[tid] = lnb[tid]; }

    int rowA[4], srcA[4];
    float2 stA[4];
    #pragma unroll
    for (int t = 0; t < 4; t++) {
        int f = t * 256 + tid;
        int row = f >> 3;
        rowA[t] = row;
        int m = m0 + row;
        int src;
        if (LNMODE == 1) {
            int w = m / NWIN, n = m % NWIN;
            int bb = w >> 6, wi = w & 63;
            int wy = wi >> 3, wx = wi & 7;
            int hy = wy * WS + n / WS, hx = wx * WS + n % WS;
            int sy = hy + SSH; if (sy >= HH) sy -= HH;
            int sx = hx + SSH; if (sx >= WW) sx -= WW;
            src = bb * (HH * WW) + sy * WW + sx;
        } else {
            src = m;
        }
        srcA[t] = src;
        stA[t] = __ldg(&stats[src]);
    }
    const int cg = tid & 7;

    float4 ra[4];
    uint2 rb[4];
    auto ldg_chunk = [&](int c) {
        const int k0 = c * 32;
        #pragma unroll
        for (int t = 0; t < 4; t++) {
            ra[t] = *reinterpret_cast<const float4*>(X + (size_t)srcA[t] * KDIM + k0 + cg * 4);
            rb[t] = *reinterpret_cast<const uint2*>(Wt + (size_t)(n0 + rowA[t]) * KDIM + k0 + cg * 4);
        }
    };
    auto sts_chunk = [&](int c, int s) {
        const int k0 = c * 32;
        __half* As = sm + s * STAGE;
        __half* Bs = As + 128 * LDKH;
        const float4 g4 = *reinterpret_cast<const float4*>(gS + k0 + cg * 4);
        const float4 b4 = *reinterpret_cast<const float4*>(bS + k0 + cg * 4);
        #pragma unroll
        for (int t = 0; t < 4; t++) {
            float mu = stA[t].x, inv = stA[t].y;
            float4 v = ra[t];
            __half2 h01 = __floats2half2_rn((v.x - mu) * inv * g4.x + b4.x,
                                            (v.y - mu) * inv * g4.y + b4.y);
            __half2 h23 = __floats2half2_rn((v.z - mu) * inv * g4.z + b4.z,
                                            (v.w - mu) * inv * g4.w + b4.w);
            uint2 pk = { *reinterpret_cast<uint32_t*>(&h01), *reinterpret_cast<uint32_t*>(&h23) };
            *reinterpret_cast<uint2*>(As + rowA[t] * LDKH + cg * 4) = pk;
            *reinterpret_cast<uint2*>(Bs + rowA[t] * LDKH + cg * 4) = rb[t];
        }
    };

    float acc[4][4][4];
    #pragma unroll
    for (int i = 0; i < 4; i++)
        #pragma unroll
        for (int j = 0; j < 4; j++)
            #pragma unroll
            for (int e = 0; e < 4; e++) acc[i][j][e] = 0.0f;

    ldg_chunk(0);
    __syncthreads();
    sts_chunk(0, 0);
    if (NC > 1) ldg_chunk(1);
    __syncthreads();

    for (int c = 0; c < NC; c++) {
        int s = c & 1;
        chunk_mma<LDKH, 32>(sm + s * STAGE, sm + s * STAGE + 128 * LDKH, wm, wn, g, t4, acc);
        if (c + 1 < NC) {
            __syncthreads();
            sts_chunk(c + 1, s ^ 1);
            if (c + 2 < NC) ldg_chunk(c + 2);
            __syncthreads();
        }
    }
    gemm_epilogue<MODE, NDIM>(acc, m0, n0, wm, wn, g, t4, bias, Out, nullptr);
}

// ---------------- LN stats: warp per token -> {mu, rsig} ----------------
__global__ __launch_bounds__(256)
void ln_stats_kernel(const float* __restrict__ x, float2* __restrict__ st)
{
    int t = blockIdx.x * 8 + (threadIdx.x >> 5);
    int lane = threadIdx.x & 31;
    const float4* rp = reinterpret_cast<const float4*>(x + (size_t)t * CC);
    float4 a = rp[lane], c = rp[lane + 32];
    float s  = a.x + a.y + a.z + a.w + c.x + c.y + c.z + c.w;
    float s2 = a.x * a.x + a.y * a.y + a.z * a.z + a.w * a.w
             + c.x * c.x + c.y * c.y + c.z * c.z + c.w * c.w;
    #pragma unroll
    for (int o = 16; o > 0; o >>= 1) {
        s  += __shfl_xor_sync(0xffffffff, s, o);
        s2 += __shfl_xor_sync(0xffffffff, s2, o);
    }
    if (lane == 0) {
        float mu  = s * (1.0f / CC);
        float var = s2 * (1.0f / CC) - mu * mu;
        st[t] = make_float2(mu, rsqrtf(var + LN_EPS));
    }
}

// ---------------- weight transpose + fp16 round ----------------
__global__ void transpose_kernel(const float* __restrict__ W, __half* __restrict__ Wt, int K, int N)
{
    __shared__ float t[32][33];
    int k0 = blockIdx.y * 32, n0 = blockIdx.x * 32;
    int tx = threadIdx.x, ty = threadIdx.y;
    for (int i = ty; i < 32; i += 8) t[i][tx] = W[(size_t)(k0 + i) * N + n0 + tx];
    __syncthreads();
    for (int i = ty; i < 32; i += 8) Wt[(size_t)(n0 + i) * K + k0 + tx] = __float2half_rn(t[tx][i]);
}

// ---------------- windowed attention: register-cached K (score) and V (PV) ----------------
__global__ __launch_bounds__(256)
void attn_kernel(const __half* __restrict__ qkv,
                 const float* __restrict__ rel_bias,
                 __half* __restrict__ out)
{
    int w    = blockIdx.x;
    int head = blockIdx.y;
    int tid  = threadIdx.x;

    __shared__ __align__(16) float q[NWIN][34];   // 8B-aligned rows
    __shared__ __align__(16) float k[NWIN][34];
    __shared__ float v[NWIN][HD + 1];
    __shared__ float s[NWIN][52];
    __shared__ float bias_s[169];
    __shared__ int   code[NWIN];

    for (int i = tid; i < 169; i += 256)
        bias_s[i] = rel_bias[i * HEADS + head];

    if (tid < NWIN) {
        int wi = w % NWB;
        int wy = wi >> 3, wx = wi & 7;
        int yi = tid / WS, xi = tid % WS;
        int gy = wy * WS + yi, gx = wx * WS + xi;
        int r = (gy < HH - WS ? 0 : (gy < HH - SSH ? 1 : 2)) * 3
              + (gx < WW - WS ? 0 : (gx < WW - SSH ? 1 : 2));
        code[tid] = (yi * 13 + xi) | (r << 16);
    }

    for (int idx = tid; idx < NWIN * (HD / 2); idx += 256) {
        int n = idx >> 4, dp = idx & 15, d = dp * 2;
        size_t base = ((size_t)(w * NWIN + n)) * (3 * CC) + head * HD + d;
        float2 qf = __half22float2(*reinterpret_cast<const __half2*>(qkv + base));
        float2 kf = __half22float2(*reinterpret_cast<const __half2*>(qkv + base + CC));
        float2 vf = __half22float2(*reinterpret_cast<const __half2*>(qkv + base + 2 * CC));
        q[n][d] = qf.x; q[n][d + 1] = qf.y;
        k[n][d] = kf.x; k[n][d + 1] = kf.y;
        v[n][d] = vf.x; v[n][d + 1] = vf.y;
    }
    __syncthreads();

    // ---- score phase: group g = tid>>6 owns rows i≡g (mod 4); lane-in-group l owns column j=l.
    // k[l] cached in 16 packed f32x2 registers; q[i] reads are warp-uniform broadcasts.
    {
        const int gidx = tid >> 6, l = tid & 63;
        unsigned long long kreg[16];
        if (l < NWIN) {
            const unsigned long long* kp = reinterpret_cast<const unsigned long long*>(&k[l][0]);
            #pragma unroll
            for (int dp = 0; dp < 16; dp++) kreg[dp] = kp[dp];
            const int cj = code[l];
            for (int i = gidx; i < NWIN; i += 4) {
                const unsigned long long* qp = reinterpret_cast<const unsigned long long*>(&q[i][0]);
                unsigned long long acc2 = 0ull;
                #pragma unroll
                for (int dp = 0; dp < 16; dp++) {
                    unsigned long long qv = qp[dp];
                    asm("fma.rn.f32x2 %0, %1, %2, %0;" : "+l"(acc2) : "l"(qv), "l"(kreg[dp]));
                }
                float dot = __uint_as_float((uint32_t)acc2)
                          + __uint_as_float((uint32_t)(acc2 >> 32));
                int ci = code[i];
                int rp = (ci & 0xffff) - (cj & 0xffff) + 84;
                float mask = ((ci ^ cj) & 0xffff0000) ? -100.0f : 0.0f;
                s[i][l] = dot * ATT_SCALE + bias_s[rp] + mask;
            }
        }
    }
    __syncthreads();

    // ---- softmax: warp per row
    int warp = tid >> 5, lane = tid & 31;
    for (int i = warp; i < NWIN; i += 8) {
        float m = -1e30f;
        for (int j = lane; j < NWIN; j += 32) m = fmaxf(m, s[i][j]);
        #pragma unroll
        for (int o = 16; o > 0; o >>= 1) m = fmaxf(m, __shfl_xor_sync(0xffffffff, m, o));
        float sum = 0.0f;
        for (int j = lane; j < NWIN; j += 32) { float e = __expf(s[i][j] - m); s[i][j] = e; sum += e; }
        #pragma unroll
        for (int o = 16; o > 0; o >>= 1) sum += __shfl_xor_sync(0xffffffff, sum, o);
        float inv = 1.0f / sum;
        for (int j = lane; j < NWIN; j += 32) s[i][j] *= inv;
    }
    __syncthreads();

    // ---- PV phase: lane owns column d=lane; v[:, lane] cached in 49 registers;
    // s[i][j] reads are warp-uniform broadcasts.
    {
        float vreg[NWIN];
        #pragma unroll
        for (int j = 0; j < NWIN; j++) vreg[j] = v[j][lane];
        for (int i = warp; i < NWIN; i += 8) {
            float acc = 0.0f;
            #pragma unroll
            for (int j = 0; j < NWIN; j++) acc += s[i][j] * vreg[j];
            out[((size_t)(w * NWIN + i)) * CC + head * HD + lane] = __float2half_rn(acc);
        }
    }
}

// ---------------- launcher ----------------
extern "C" void kernel_launch(void* const* d_in, const int* in_sizes, int n_in,
                              void* d_out, int out_size)
{
    (void)in_sizes; (void)n_in; (void)out_size;
    const float* x        = (const float*)d_in[0];
    const float* qkv_w    = (const float*)d_in[1];
    const float* qkv_b    = (const float*)d_in[2];
    const float* proj_w   = (const float*)d_in[3];
    const float* proj_b   = (const float*)d_in[4];
    const float* rel_bias = (const float*)d_in[5];
    const float* ln1_g    = (const float*)d_in[6];
    const float* ln1_b    = (const float*)d_in[7];
    const float* ln2_g    = (const float*)d_in[8];
    const float* ln2_b    = (const float*)d_in[9];
    const float* mlp_w1   = (const float*)d_in[10];
    const float* mlp_b1   = (const float*)d_in[11];
    const float* mlp_w2   = (const float*)d_in[12];
    const float* mlp_b2   = (const float*)d_in[13];
    float* out = (float*)d_out;

    __half *qkvb, *att, *hbuf, *wq, *wp, *w1, *w2;
    float *x1;
    float2 *st1, *st2;
    cudaGetSymbolAddress((void**)&qkvb, g_qkv);
    cudaGetSymbolAddress((void**)&att,  g_att);
    cudaGetSymbolAddress((void**)&x1,   g_x1);
    cudaGetSymbolAddress((void**)&hbuf, g_h);
    cudaGetSymbolAddress((void**)&st1,  g_st1);
    cudaGetSymbolAddress((void**)&st2,  g_st2);
    cudaGetSymbolAddress((void**)&wq,   g_wq);
    cudaGetSymbolAddress((void**)&wp,   g_wp);
    cudaGetSymbolAddress((void**)&w1,   g_w1);
    cudaGetSymbolAddress((void**)&w2,   g_w2);

    const int SMEM2 = 2 * 2 * 128 * LDKH2 * 2;               // 73728 B
    const int SMEML = 2 * 2 * 128 * LDKH * 2 + 2 * 256 * 4;  // 40960 + 2048
    cudaFuncSetAttribute(mma_gemm<1, 256,  256>, cudaFuncAttributeMaxDynamicSharedMemorySize, SMEM2);
    cudaFuncSetAttribute(mma_gemm<3, 1024, 256>, cudaFuncAttributeMaxDynamicSharedMemorySize, SMEM2);
    cudaFuncSetAttribute(mma_gemm_ln<0, 1, 256,  768>, cudaFuncAttributeMaxDynamicSharedMemorySize, SMEML);
    cudaFuncSetAttribute(mma_gemm_ln<2, 2, 256, 1024>, cudaFuncAttributeMaxDynamicSharedMemorySize, SMEML);

    // 1. LN1 stats
    ln_stats_kernel<<<TOK / 8, 256>>>(x, st1);
    // 2-5. weight transposes + fp16 rounding (tiny)
    transpose_kernel<<<dim3(768 / 32, 256 / 32),  dim3(32, 8)>>>(qkv_w,  wq, 256, 768);
    transpose_kernel<<<dim3(256 / 32, 256 / 32),  dim3(32, 8)>>>(proj_w, wp, 256, 256);
    transpose_kernel<<<dim3(1024 / 32, 256 / 32), dim3(32, 8)>>>(mlp_w1, w1, 256, 1024);
    transpose_kernel<<<dim3(256 / 32, 1024 / 32), dim3(32, 8)>>>(mlp_w2, w2, 1024, 256);
    // 6. QKV GEMM with fused LN1 + shift + window partition (half out)
    mma_gemm_ln<0, 1, 256, 768><<<dim3(768 / 128, TOK / 128), 256, SMEML>>>(
        x, wq, st1, ln1_g, ln1_b, qkv_b, qkvb);
    // 7. windowed attention (half in/out)
    attn_kernel<<<dim3(NWTOT, HEADS), 256>>>(qkvb, rel_bias, att);
    // 8. proj GEMM + window reverse + roll + residual (float out)
    mma_gemm<1, 256, 256><<<dim3(256 / 128, TOK / 128), 256, SMEM2>>>(att, wp, proj_b, x1, x);
    // 9. LN2 stats
    ln_stats_kernel<<<TOK / 8, 256>>>(x1, st2);
    // 10. MLP1 GEMM with fused LN2 + GELU epilogue (half out)
    mma_gemm_ln<2, 2, 256, 1024><<<dim3(1024 / 128, TOK / 128), 256, SMEML>>>(
        x1, w1, st2, ln2_g, ln2_b, mlp_b1, hbuf);
    // 11. MLP2 + residual -> d_out (float out)
    mma_gemm<3, 1024, 256><<<dim3(256 / 128, TOK / 128), 256, SMEM2>>>(hbuf, w2, mlp_b2, out, x1);
}

// round 10
// speedup vs baseline: 1.2899x; 1.2899x over previous
#include <cuda_runtime.h>
#include <cuda_fp16.h>
#include <math.h>
#include <cstdint>

// ---------------- problem constants ----------------
#define TOK    100352          // 32 * 56 * 56 tokens
#define CC     256
#define HEADS  8
#define HD     32
#define WS     7
#define NWIN   49
#define MLPD   1024
#define HH     56
#define WW     56
#define SSH    3
#define NWB    64
#define NWTOT  2048
#define ATT_SCALE 0.17677669529663687f
#define LN_EPS 1e-5f

// ---------------- scratch (static device globals; no allocation) ----------------
__device__ __half g_xw  [(size_t)TOK * CC];     // LN1+shift output (fp16)
__device__ __half g_xn2 [(size_t)TOK * CC];     // LN2 output (fp16)
__device__ __half g_qkv [(size_t)TOK * 3 * CC];
__device__ __half g_att [(size_t)TOK * CC];
__device__ float  g_x1  [(size_t)TOK * CC];
__device__ __half g_h   [(size_t)TOK * MLPD];
// transposed weights [N,K] row-major, fp16
__device__ __half g_wq [768 * 256];
__device__ __half g_wp [256 * 256];
__device__ __half g_w1 [1024 * 256];
__device__ __half g_w2 [256 * 1024];

// ---------------- helpers ----------------
__device__ __forceinline__ uint32_t smem_u32(const void* p) {
    uint32_t a;
    asm("{ .reg .u64 t; cvta.to.shared.u64 t, %1; cvt.u32.u64 %0, t; }" : "=r"(a) : "l"(p));
    return a;
}
__device__ __forceinline__ void cp_async16(uint32_t dst, const void* src) {
    asm volatile("cp.async.cg.shared.global [%0], [%1], 16;" :: "r"(dst), "l"(src));
}
#define CP_COMMIT() asm volatile("cp.async.commit_group;" ::: "memory")

// m16n8k16 fp16 MMA, fp32 accumulate
__device__ __forceinline__ void mma_f16(float* c,
                                        uint32_t a0, uint32_t a1, uint32_t a2, uint32_t a3,
                                        uint32_t b0, uint32_t b1) {
    asm volatile(
        "mma.sync.aligned.m16n8k16.row.col.f32.f16.f16.f32 "
        "{%0,%1,%2,%3}, {%4,%5,%6,%7}, {%8,%9}, {%0,%1,%2,%3};"
        : "+f"(c[0]), "+f"(c[1]), "+f"(c[2]), "+f"(c[3])
        : "r"(a0), "r"(a1), "r"(a2), "r"(a3), "r"(b0), "r"(b1));
}

#define LDKH2 72   // padded row stride (halves) for 64-half chunks

// scalar-LDS K-step MMA over 64-half chunk (round-7 proven form)
__device__ __forceinline__ void chunk_mma64(const __half* As, const __half* Bs,
                                            int wm, int wn, int g, int t4,
                                            float acc[4][4][4]) {
    #pragma unroll
    for (int ks = 0; ks < 4; ks++) {
        const int kb = ks * 16;
        uint32_t bf[4][2];
        #pragma unroll
        for (int ni = 0; ni < 4; ni++) {
            const __half* bp = Bs + (wn + ni * 8 + g) * LDKH2 + kb + t4 * 2;
            bf[ni][0] = *reinterpret_cast<const uint32_t*>(bp);
            bf[ni][1] = *reinterpret_cast<const uint32_t*>(bp + 8);
        }
        #pragma unroll
        for (int mi = 0; mi < 4; mi++) {
            const __half* ap = As + (wm + mi * 16 + g) * LDKH2 + kb + t4 * 2;
            uint32_t a0 = *reinterpret_cast<const uint32_t*>(ap);
            uint32_t a1 = *reinterpret_cast<const uint32_t*>(ap + 8 * LDKH2);
            uint32_t a2 = *reinterpret_cast<const uint32_t*>(ap + 8);
            uint32_t a3 = *reinterpret_cast<const uint32_t*>(ap + 8 * LDKH2 + 8);
            #pragma unroll
            for (int ni = 0; ni < 4; ni++)
                mma_f16(acc[mi][ni], a0, a1, a2, a3, bf[ni][0], bf[ni][1]);
        }
    }
}

// shared epilogue. MODE 0: half out (QKV)  MODE 1: float res+scatter (proj)
// MODE 2: half gelu out (MLP1)  MODE 3: float res out (MLP2)
template<int MODE, int NDIM>
__device__ __forceinline__ void gemm_epilogue(float acc[4][4][4],
                                              int m0, int n0, int wm, int wn, int g, int t4,
                                              const float* __restrict__ bias,
                                              void* __restrict__ OutV,
                                              const float* __restrict__ res) {
    #pragma unroll
    for (int mi = 0; mi < 4; mi++) {
        #pragma unroll
        for (int h = 0; h < 2; h++) {
            int m = m0 + wm + mi * 16 + g + h * 8;
            size_t drow;
            if (MODE == 1) {
                int w = m / NWIN, ntok = m % NWIN;
                int bb2 = w / NWB, wi = w % NWB;
                int wy = wi >> 3, wx = wi & 7;
                int hy = wy * WS + ntok / WS, hx = wx * WS + ntok % WS;
                int oy = (hy + SSH) % HH, ox = (hx + SSH) % WW;
                drow = ((size_t)bb2 * HH * WW + oy * WW + ox) * CC;
            } else {
                drow = (size_t)m * NDIM;
            }
            #pragma unroll
            for (int ni = 0; ni < 4; ni++) {
                int n = n0 + wn + ni * 8 + 2 * t4;
                float2 bv = *reinterpret_cast<const float2*>(bias + n);
                float vx = acc[mi][ni][2 * h + 0] + bv.x;
                float vy = acc[mi][ni][2 * h + 1] + bv.y;
                if (MODE == 1 || MODE == 3) {
                    float2 r = *reinterpret_cast<const float2*>(res + drow + n);
                    float2 o = { vx + r.x, vy + r.y };
                    *reinterpret_cast<float2*>((float*)OutV + drow + n) = o;
                } else {
                    if (MODE == 2) {
                        vx = 0.5f * vx * (1.0f + erff(vx * 0.70710678118654752f));
                        vy = 0.5f * vy * (1.0f + erff(vy * 0.70710678118654752f));
                    }
                    *reinterpret_cast<__half2*>((__half*)OutV + drow + n) =
                        __floats2half2_rn(vx, vy);
                }
            }
        }
    }
}

// ---------------- cp.async fp16 GEMM, 64-half K chunks (all four GEMMs) ----------------
template<int MODE, int KDIM, int NDIM>
__global__ __launch_bounds__(256)
void mma_gemm(const __half* __restrict__ A, const __half* __restrict__ Wt,
              const float* __restrict__ bias, void* __restrict__ Out,
              const float* __restrict__ res)
{
    extern __shared__ char smraw[];
    __half* sm = reinterpret_cast<__half*>(smraw);
    const uint32_t sbase = smem_u32(smraw);

    const int tid  = threadIdx.x;
    const int wid  = tid >> 5, lane = tid & 31;
    const int g    = lane >> 2, t4 = lane & 3;
    const int wm   = (wid & 1) * 64;
    const int wn   = (wid >> 1) * 32;
    const int m0   = blockIdx.y * 128;
    const int n0   = blockIdx.x * 128;

    constexpr int NC = KDIM / 64;
    constexpr int STAGE = 2 * 128 * LDKH2;

    auto load_chunk = [&](int c, int s) {
        const int k0 = c * 64;
        uint32_t sa  = sbase + (uint32_t)(s * STAGE) * 2u;
        uint32_t sb2 = sa + 128u * LDKH2 * 2u;
        #pragma unroll
        for (int t = 0; t < 4; t++) {
            int f = t * 256 + tid;
            int row = f >> 3, seg = f & 7;
            cp_async16(sa  + (uint32_t)(row * LDKH2) * 2u + seg * 16,
                       A  + (size_t)(m0 + row) * KDIM + k0 + seg * 8);
            cp_async16(sb2 + (uint32_t)(row * LDKH2) * 2u + seg * 16,
                       Wt + (size_t)(n0 + row) * KDIM + k0 + seg * 8);
        }
        CP_COMMIT();
    };

    float acc[4][4][4];
    #pragma unroll
    for (int i = 0; i < 4; i++)
        #pragma unroll
        for (int j = 0; j < 4; j++)
            #pragma unroll
            for (int e = 0; e < 4; e++) acc[i][j][e] = 0.0f;

    load_chunk(0, 0);
    if (NC > 1) load_chunk(1, 1);

    for (int c = 0; c < NC; c++) {
        if (c + 1 < NC) asm volatile("cp.async.wait_group 1;" ::: "memory");
        else            asm volatile("cp.async.wait_group 0;" ::: "memory");
        __syncthreads();
        const __half* As = sm + (c & 1) * STAGE;
        const __half* Bs = As + 128 * LDKH2;
        chunk_mma64(As, Bs, wm, wn, g, t4, acc);
        if (c + 2 < NC) {
            __syncthreads();
            load_chunk(c + 2, c & 1);
        }
    }
    gemm_epilogue<MODE, NDIM>(acc, m0, n0, wm, wn, g, t4, bias, Out, res);
}

// ---------------- fused LN apply: warp/token, stats + normalize -> fp16 ----------------
// SHIFT: gather via roll(-3,-3) + window partition (LN1); else plain rows (LN2).
template<bool SHIFT>
__global__ __launch_bounds__(256)
void ln_apply_kernel(const float* __restrict__ x,
                     const float* __restrict__ g,
                     const float* __restrict__ b,
                     __half* __restrict__ out)
{
    int t = blockIdx.x * 8 + (threadIdx.x >> 5);
    int lane = threadIdx.x & 31;

    int src;
    if (SHIFT) {
        int w = t / NWIN, n = t % NWIN;
        int bb = w >> 6, wi = w & 63;
        int wy = wi >> 3, wx = wi & 7;
        int hy = wy * WS + n / WS, hx = wx * WS + n % WS;
        int sy = hy + SSH; if (sy >= HH) sy -= HH;
        int sx = hx + SSH; if (sx >= WW) sx -= WW;
        src = bb * (HH * WW) + sy * WW + sx;
    } else {
        src = t;
    }

    const float4* rp = reinterpret_cast<const float4*>(x + (size_t)src * CC);
    float4 a = rp[lane], c = rp[lane + 32];
    float s  = a.x + a.y + a.z + a.w + c.x + c.y + c.z + c.w;
    float s2 = a.x * a.x + a.y * a.y + a.z * a.z + a.w * a.w
             + c.x * c.x + c.y * c.y + c.z * c.z + c.w * c.w;
    #pragma unroll
    for (int o = 16; o > 0; o >>= 1) {
        s  += __shfl_xor_sync(0xffffffff, s, o);
        s2 += __shfl_xor_sync(0xffffffff, s2, o);
    }
    float mu  = s * (1.0f / CC);
    float var = s2 * (1.0f / CC) - mu * mu;
    float inv = rsqrtf(var + LN_EPS);

    const float4* gp = reinterpret_cast<const float4*>(g);
    const float4* bp = reinterpret_cast<const float4*>(b);
    uint2* op = reinterpret_cast<uint2*>(out + (size_t)t * CC);
    #pragma unroll
    for (int h = 0; h < 2; h++) {
        float4 v = h ? c : a;
        float4 gg = gp[lane + h * 32], bb4 = bp[lane + h * 32];
        __half2 h01 = __floats2half2_rn((v.x - mu) * inv * gg.x + bb4.x,
                                        (v.y - mu) * inv * gg.y + bb4.y);
        __half2 h23 = __floats2half2_rn((v.z - mu) * inv * gg.z + bb4.z,
                                        (v.w - mu) * inv * gg.w + bb4.w);
        uint2 pk = { *reinterpret_cast<uint32_t*>(&h01), *reinterpret_cast<uint32_t*>(&h23) };
        op[lane + h * 32] = pk;
    }
}

// ---------------- weight transpose + fp16 round ----------------
__global__ void transpose_kernel(const float* __restrict__ W, __half* __restrict__ Wt, int K, int N)
{
    __shared__ float t[32][33];
    int k0 = blockIdx.y * 32, n0 = blockIdx.x * 32;
    int tx = threadIdx.x, ty = threadIdx.y;
    for (int i = ty; i < 32; i += 8) t[i][tx] = W[(size_t)(k0 + i) * N + n0 + tx];
    __syncthreads();
    for (int i = ty; i < 32; i += 8) Wt[(size_t)(n0 + i) * K + k0 + tx] = __float2half_rn(t[tx][i]);
}

// ---------------- windowed attention (round-7 proven form) ----------------
__global__ __launch_bounds__(256)
void attn_kernel(const __half* __restrict__ qkv,
                 const float* __restrict__ rel_bias,
                 __half* __restrict__ out)
{
    int w    = blockIdx.x;
    int head = blockIdx.y;
    int tid  = threadIdx.x;

    __shared__ float q[NWIN][HD];
    __shared__ float k[NWIN][HD + 1];
    __shared__ float v[NWIN][HD + 1];
    __shared__ float s[NWIN][52];
    __shared__ float bias_s[169];
    __shared__ int   code[NWIN];

    for (int i = tid; i < 169; i += 256)
        bias_s[i] = rel_bias[i * HEADS + head];

    if (tid < NWIN) {
        int wi = w % NWB;
        int wy = wi >> 3, wx = wi & 7;
        int yi = tid / WS, xi = tid % WS;
        int gy = wy * WS + yi, gx = wx * WS + xi;
        int r = (gy < HH - WS ? 0 : (gy < HH - SSH ? 1 : 2)) * 3
              + (gx < WW - WS ? 0 : (gx < WW - SSH ? 1 : 2));
        code[tid] = (yi * 13 + xi) | (r << 16);
    }

    for (int idx = tid; idx < NWIN * (HD / 2); idx += 256) {
        int n = idx >> 4, dp = idx & 15, d = dp * 2;
        size_t base = ((size_t)(w * NWIN + n)) * (3 * CC) + head * HD + d;
        float2 qf = __half22float2(*reinterpret_cast<const __half2*>(qkv + base));
        float2 kf = __half22float2(*reinterpret_cast<const __half2*>(qkv + base + CC));
        float2 vf = __half22float2(*reinterpret_cast<const __half2*>(qkv + base + 2 * CC));
        q[n][d] = qf.x; q[n][d + 1] = qf.y;
        k[n][d] = kf.x; k[n][d + 1] = kf.y;
        v[n][d] = vf.x; v[n][d + 1] = vf.y;
    }
    __syncthreads();

    for (int idx = tid; idx < NWIN * NWIN; idx += 256) {
        int i = idx / NWIN, j = idx % NWIN;
        float dot = 0.0f;
        #pragma unroll
        for (int d = 0; d < HD; d++) dot += q[i][d] * k[j][d];
        int ci = code[i], cj = code[j];
        int rp = (ci & 0xffff) - (cj & 0xffff) + 84;
        float mask = ((ci ^ cj) & 0xffff0000) ? -100.0f : 0.0f;
        s[i][j] = dot * ATT_SCALE + bias_s[rp] + mask;
    }
    __syncthreads();

    int warp = tid >> 5, lane = tid & 31;
    for (int i = warp; i < NWIN; i += 8) {
        float m = -1e30f;
        for (int j = lane; j < NWIN; j += 32) m = fmaxf(m, s[i][j]);
        #pragma unroll
        for (int o = 16; o > 0; o >>= 1) m = fmaxf(m, __shfl_xor_sync(0xffffffff, m, o));
        float sum = 0.0f;
        for (int j = lane; j < NWIN; j += 32) { float e = __expf(s[i][j] - m); s[i][j] = e; sum += e; }
        #pragma unroll
        for (int o = 16; o > 0; o >>= 1) sum += __shfl_xor_sync(0xffffffff, sum, o);
        float inv = 1.0f / sum;
        for (int j = lane; j < NWIN; j += 32) s[i][j] *= inv;
    }
    __syncthreads();

    for (int idx = tid; idx < NWIN * HD; idx += 256) {
        int i = idx >> 5, d = idx & 31;
        float acc = 0.0f;
        #pragma unroll
        for (int j = 0; j < NWIN; j++) acc += s[i][j] * v[j][d];
        out[((size_t)(w * NWIN + i)) * CC + head * HD + d] = __float2half_rn(acc);
    }
}

// ---------------- launcher ----------------
extern "C" void kernel_launch(void* const* d_in, const int* in_sizes, int n_in,
                              void* d_out, int out_size)
{
    (void)in_sizes; (void)n_in; (void)out_size;
    const float* x        = (const float*)d_in[0];
    const float* qkv_w    = (const float*)d_in[1];
    const float* qkv_b    = (const float*)d_in[2];
    const float* proj_w   = (const float*)d_in[3];
    const float* proj_b   = (const float*)d_in[4];
    const float* rel_bias = (const float*)d_in[5];
    const float* ln1_g    = (const float*)d_in[6];
    const float* ln1_b    = (const float*)d_in[7];
    const float* ln2_g    = (const float*)d_in[8];
    const float* ln2_b    = (const float*)d_in[9];
    const float* mlp_w1   = (const float*)d_in[10];
    const float* mlp_b1   = (const float*)d_in[11];
    const float* mlp_w2   = (const float*)d_in[12];
    const float* mlp_b2   = (const float*)d_in[13];
    float* out = (float*)d_out;

    __half *xw, *xn2, *qkvb, *att, *hbuf, *wq, *wp, *w1, *w2;
    float *x1;
    cudaGetSymbolAddress((void**)&xw,   g_xw);
    cudaGetSymbolAddress((void**)&xn2,  g_xn2);
    cudaGetSymbolAddress((void**)&qkvb, g_qkv);
    cudaGetSymbolAddress((void**)&att,  g_att);
    cudaGetSymbolAddress((void**)&x1,   g_x1);
    cudaGetSymbolAddress((void**)&hbuf, g_h);
    cudaGetSymbolAddress((void**)&wq,   g_wq);
    cudaGetSymbolAddress((void**)&wp,   g_wp);
    cudaGetSymbolAddress((void**)&w1,   g_w1);
    cudaGetSymbolAddress((void**)&w2,   g_w2);

    const int SMEM2 = 2 * 2 * 128 * LDKH2 * 2;   // 73728 B
    cudaFuncSetAttribute(mma_gemm<0, 256,  768>, cudaFuncAttributeMaxDynamicSharedMemorySize, SMEM2);
    cudaFuncSetAttribute(mma_gemm<1, 256,  256>, cudaFuncAttributeMaxDynamicSharedMemorySize, SMEM2);
    cudaFuncSetAttribute(mma_gemm<2, 256, 1024>, cudaFuncAttributeMaxDynamicSharedMemorySize, SMEM2);
    cudaFuncSetAttribute(mma_gemm<3, 1024, 256>, cudaFuncAttributeMaxDynamicSharedMemorySize, SMEM2);

    // 1. LN1 + shift + window partition -> fp16 xw
    ln_apply_kernel<true><<<TOK / 8, 256>>>(x, ln1_g, ln1_b, xw);
    // 2-5. weight transposes + fp16 rounding (tiny)
    transpose_kernel<<<dim3(768 / 32, 256 / 32),  dim3(32, 8)>>>(qkv_w,  wq, 256, 768);
    transpose_kernel<<<dim3(256 / 32, 256 / 32),  dim3(32, 8)>>>(proj_w, wp, 256, 256);
    transpose_kernel<<<dim3(1024 / 32, 256 / 32), dim3(32, 8)>>>(mlp_w1, w1, 256, 1024);
    transpose_kernel<<<dim3(256 / 32, 1024 / 32), dim3(32, 8)>>>(mlp_w2, w2, 1024, 256);
    // 6. QKV GEMM (half out)
    mma_gemm<0, 256, 768><<<dim3(768 / 128, TOK / 128), 256, SMEM2>>>(xw, wq, qkv_b, qkvb, nullptr);
    // 7. windowed attention (half in/out)
    attn_kernel<<<dim3(NWTOT, HEADS), 256>>>(qkvb, rel_bias, att);
    // 8. proj GEMM + window reverse + roll + residual (float out)
    mma_gemm<1, 256, 256><<<dim3(256 / 128, TOK / 128), 256, SMEM2>>>(att, wp, proj_b, x1, x);
    // 9. LN2 -> fp16 xn2
    ln_apply_kernel<false><<<TOK / 8, 256>>>(x1, ln2_g, ln2_b, xn2);
    // 10. MLP1 + GELU (half out)
    mma_gemm<2, 256, 1024><<<dim3(1024 / 128, TOK / 128), 256, SMEM2>>>(xn2, w1, mlp_b1, hbuf, nullptr);
    // 11. MLP2 + residual -> d_out (float out)
    mma_gemm<3, 1024, 256><<<dim3(256 / 128, TOK / 128), 256, SMEM2>>>(hbuf, w2, mlp_b2, out, x1);
}

// round 11
// speedup vs baseline: 1.3010x; 1.0086x over previous
#include <cuda_runtime.h>
#include <cuda_fp16.h>
#include <math.h>
#include <cstdint>

// ---------------- problem constants ----------------
#define TOK    100352          // 32 * 56 * 56 tokens
#define CC     256
#define HEADS  8
#define HD     32
#define WS     7
#define NWIN   49
#define MLPD   1024
#define HH     56
#define WW     56
#define SSH    3
#define NWB    64
#define NWTOT  2048
#define ATT_SCALE 0.17677669529663687f
#define LN_EPS 1e-5f

// ---------------- scratch (static device globals; no allocation) ----------------
__device__ __half g_xw  [(size_t)TOK * CC];     // LN1+shift output (fp16)
__device__ __half g_xn2 [(size_t)TOK * CC];     // LN2 output (fp16)
__device__ __half g_qkv [(size_t)TOK * 3 * CC];
__device__ __half g_att [(size_t)TOK * CC];
__device__ float  g_x1  [(size_t)TOK * CC];
__device__ __half g_h   [(size_t)TOK * MLPD];
// transposed weights [N,K] row-major, fp16
__device__ __half g_wq [768 * 256];
__device__ __half g_wp [256 * 256];
__device__ __half g_w1 [1024 * 256];
__device__ __half g_w2 [256 * 1024];

// ---------------- helpers ----------------
__device__ __forceinline__ uint32_t smem_u32(const void* p) {
    uint32_t a;
    asm("{ .reg .u64 t; cvta.to.shared.u64 t, %1; cvt.u32.u64 %0, t; }" : "=r"(a) : "l"(p));
    return a;
}
__device__ __forceinline__ void cp_async16(uint32_t dst, const void* src) {
    asm volatile("cp.async.cg.shared.global [%0], [%1], 16;" :: "r"(dst), "l"(src));
}
#define CP_COMMIT() asm volatile("cp.async.commit_group;" ::: "memory")

// m16n8k16 fp16 MMA, fp32 accumulate
__device__ __forceinline__ void mma_f16(float* c,
                                        uint32_t a0, uint32_t a1, uint32_t a2, uint32_t a3,
                                        uint32_t b0, uint32_t b1) {
    asm volatile(
        "mma.sync.aligned.m16n8k16.row.col.f32.f16.f16.f32 "
        "{%0,%1,%2,%3}, {%4,%5,%6,%7}, {%8,%9}, {%0,%1,%2,%3};"
        : "+f"(c[0]), "+f"(c[1]), "+f"(c[2]), "+f"(c[3])
        : "r"(a0), "r"(a1), "r"(a2), "r"(a3), "r"(b0), "r"(b1));
}

#define LDKH2 72   // padded row stride (halves) for 64-half chunks

// scalar-LDS K-step MMA over 64-half chunk (proven form)
__device__ __forceinline__ void chunk_mma64(const __half* As, const __half* Bs,
                                            int wm, int wn, int g, int t4,
                                            float acc[4][4][4]) {
    #pragma unroll
    for (int ks = 0; ks < 4; ks++) {
        const int kb = ks * 16;
        uint32_t bf[4][2];
        #pragma unroll
        for (int ni = 0; ni < 4; ni++) {
            const __half* bp = Bs + (wn + ni * 8 + g) * LDKH2 + kb + t4 * 2;
            bf[ni][0] = *reinterpret_cast<const uint32_t*>(bp);
            bf[ni][1] = *reinterpret_cast<const uint32_t*>(bp + 8);
        }
        #pragma unroll
        for (int mi = 0; mi < 4; mi++) {
            const __half* ap = As + (wm + mi * 16 + g) * LDKH2 + kb + t4 * 2;
            uint32_t a0 = *reinterpret_cast<const uint32_t*>(ap);
            uint32_t a1 = *reinterpret_cast<const uint32_t*>(ap + 8 * LDKH2);
            uint32_t a2 = *reinterpret_cast<const uint32_t*>(ap + 8);
            uint32_t a3 = *reinterpret_cast<const uint32_t*>(ap + 8 * LDKH2 + 8);
            #pragma unroll
            for (int ni = 0; ni < 4; ni++)
                mma_f16(acc[mi][ni], a0, a1, a2, a3, bf[ni][0], bf[ni][1]);
        }
    }
}

// shared epilogue. MODE 0: half out (QKV)  MODE 1: float res+scatter (proj)
// MODE 2: half gelu out (MLP1)  MODE 3: float res out (MLP2)
template<int MODE, int NDIM>
__device__ __forceinline__ void gemm_epilogue(float acc[4][4][4],
                                              int m0, int n0, int wm, int wn, int g, int t4,
                                              const float* __restrict__ bias,
                                              void* __restrict__ OutV,
                                              const float* __restrict__ res) {
    #pragma unroll
    for (int mi = 0; mi < 4; mi++) {
        #pragma unroll
        for (int h = 0; h < 2; h++) {
            int m = m0 + wm + mi * 16 + g + h * 8;
            size_t drow;
            if (MODE == 1) {
                int w = m / NWIN, ntok = m % NWIN;
                int bb2 = w / NWB, wi = w % NWB;
                int wy = wi >> 3, wx = wi & 7;
                int hy = wy * WS + ntok / WS, hx = wx * WS + ntok % WS;
                int oy = (hy + SSH) % HH, ox = (hx + SSH) % WW;
                drow = ((size_t)bb2 * HH * WW + oy * WW + ox) * CC;
            } else {
                drow = (size_t)m * NDIM;
            }
            #pragma unroll
            for (int ni = 0; ni < 4; ni++) {
                int n = n0 + wn + ni * 8 + 2 * t4;
                float2 bv = *reinterpret_cast<const float2*>(bias + n);
                float vx = acc[mi][ni][2 * h + 0] + bv.x;
                float vy = acc[mi][ni][2 * h + 1] + bv.y;
                if (MODE == 1 || MODE == 3) {
                    float2 r = *reinterpret_cast<const float2*>(res + drow + n);
                    float2 o = { vx + r.x, vy + r.y };
                    *reinterpret_cast<float2*>((float*)OutV + drow + n) = o;
                } else {
                    if (MODE == 2) {
                        vx = 0.5f * vx * (1.0f + erff(vx * 0.70710678118654752f));
                        vy = 0.5f * vy * (1.0f + erff(vy * 0.70710678118654752f));
                    }
                    *reinterpret_cast<__half2*>((__half*)OutV + drow + n) =
                        __floats2half2_rn(vx, vy);
                }
            }
        }
    }
}

// ---------------- cp.async fp16 GEMM, 64-half K chunks, 3-stage ring ----------------
template<int MODE, int KDIM, int NDIM>
__global__ __launch_bounds__(256)
void mma_gemm(const __half* __restrict__ A, const __half* __restrict__ Wt,
              const float* __restrict__ bias, void* __restrict__ Out,
              const float* __restrict__ res)
{
    extern __shared__ char smraw[];
    __half* sm = reinterpret_cast<__half*>(smraw);
    const uint32_t sbase = smem_u32(smraw);

    const int tid  = threadIdx.x;
    const int wid  = tid >> 5, lane = tid & 31;
    const int g    = lane >> 2, t4 = lane & 3;
    const int wm   = (wid & 1) * 64;
    const int wn   = (wid >> 1) * 32;
    const int m0   = blockIdx.y * 128;
    const int n0   = blockIdx.x * 128;

    constexpr int NC = KDIM / 64;
    constexpr int STAGE = 2 * 128 * LDKH2;          // halves per stage (A+B)

    auto load_chunk = [&](int c, int s) {
        const int k0 = c * 64;
        uint32_t sa  = sbase + (uint32_t)(s * STAGE) * 2u;
        uint32_t sb2 = sa + 128u * LDKH2 * 2u;
        #pragma unroll
        for (int t = 0; t < 4; t++) {
            int f = t * 256 + tid;
            int row = f >> 3, seg = f & 7;
            cp_async16(sa  + (uint32_t)(row * LDKH2) * 2u + seg * 16,
                       A  + (size_t)(m0 + row) * KDIM + k0 + seg * 8);
            cp_async16(sb2 + (uint32_t)(row * LDKH2) * 2u + seg * 16,
                       Wt + (size_t)(n0 + row) * KDIM + k0 + seg * 8);
        }
        CP_COMMIT();
    };

    float acc[4][4][4];
    #pragma unroll
    for (int i = 0; i < 4; i++)
        #pragma unroll
        for (int j = 0; j < 4; j++)
            #pragma unroll
            for (int e = 0; e < 4; e++) acc[i][j][e] = 0.0f;

    load_chunk(0, 0);
    load_chunk(1, 1);          // NC >= 4 always here

    int stage = 0;             // stage of chunk c
    for (int c = 0; c < NC; c++) {
        if (c + 1 < NC) asm volatile("cp.async.wait_group 1;" ::: "memory");
        else            asm volatile("cp.async.wait_group 0;" ::: "memory");
        __syncthreads();       // chunk c visible to all; stage (c-1)%3 fully consumed by all
        if (c + 2 < NC) {
            int s2 = stage + 2; if (s2 >= 3) s2 -= 3;   // == (c-1)%3, safe to overwrite
            load_chunk(c + 2, s2);
        }
        const __half* As = sm + stage * STAGE;
        const __half* Bs = As + 128 * LDKH2;
        chunk_mma64(As, Bs, wm, wn, g, t4, acc);
        if (++stage == 3) stage = 0;
    }
    gemm_epilogue<MODE, NDIM>(acc, m0, n0, wm, wn, g, t4, bias, Out, res);
}

// ---------------- fused LN apply: warp/token, stats + normalize -> fp16 ----------------
template<bool SHIFT>
__global__ __launch_bounds__(256)
void ln_apply_kernel(const float* __restrict__ x,
                     const float* __restrict__ g,
                     const float* __restrict__ b,
                     __half* __restrict__ out)
{
    int t = blockIdx.x * 8 + (threadIdx.x >> 5);
    int lane = threadIdx.x & 31;

    int src;
    if (SHIFT) {
        int w = t / NWIN, n = t % NWIN;
        int bb = w >> 6, wi = w & 63;
        int wy = wi >> 3, wx = wi & 7;
        int hy = wy * WS + n / WS, hx = wx * WS + n % WS;
        int sy = hy + SSH; if (sy >= HH) sy -= HH;
        int sx = hx + SSH; if (sx >= WW) sx -= WW;
        src = bb * (HH * WW) + sy * WW + sx;
    } else {
        src = t;
    }

    const float4* rp = reinterpret_cast<const float4*>(x + (size_t)src * CC);
    float4 a = rp[lane], c = rp[lane + 32];
    float s  = a.x + a.y + a.z + a.w + c.x + c.y + c.z + c.w;
    float s2 = a.x * a.x + a.y * a.y + a.z * a.z + a.w * a.w
             + c.x * c.x + c.y * c.y + c.z * c.z + c.w * c.w;
    #pragma unroll
    for (int o = 16; o > 0; o >>= 1) {
        s  += __shfl_xor_sync(0xffffffff, s, o);
        s2 += __shfl_xor_sync(0xffffffff, s2, o);
    }
    float mu  = s * (1.0f / CC);
    float var = s2 * (1.0f / CC) - mu * mu;
    float inv = rsqrtf(var + LN_EPS);

    const float4* gp = reinterpret_cast<const float4*>(g);
    const float4* bp = reinterpret_cast<const float4*>(b);
    uint2* op = reinterpret_cast<uint2*>(out + (size_t)t * CC);
    #pragma unroll
    for (int h = 0; h < 2; h++) {
        float4 v = h ? c : a;
        float4 gg = gp[lane + h * 32], bb4 = bp[lane + h * 32];
        __half2 h01 = __floats2half2_rn((v.x - mu) * inv * gg.x + bb4.x,
                                        (v.y - mu) * inv * gg.y + bb4.y);
        __half2 h23 = __floats2half2_rn((v.z - mu) * inv * gg.z + bb4.z,
                                        (v.w - mu) * inv * gg.w + bb4.w);
        uint2 pk = { *reinterpret_cast<uint32_t*>(&h01), *reinterpret_cast<uint32_t*>(&h23) };
        op[lane + h * 32] = pk;
    }
}

// ---------------- merged weight transpose (all 4 weights in one launch) ----------------
__global__ void transpose_all_kernel(const float* __restrict__ qkv_w,
                                     const float* __restrict__ proj_w,
                                     const float* __restrict__ mlp_w1,
                                     const float* __restrict__ mlp_w2,
                                     __half* __restrict__ wq, __half* __restrict__ wp,
                                     __half* __restrict__ w1, __half* __restrict__ w2)
{
    __shared__ float t[32][33];
    int bidx = blockIdx.x;
    const float* W; __half* Wt; int K, N, tile;
    if (bidx < 192)      { W = qkv_w;  Wt = wq; K = 256;  N = 768;  tile = bidx; }
    else if (bidx < 256) { W = proj_w; Wt = wp; K = 256;  N = 256;  tile = bidx - 192; }
    else if (bidx < 512) { W = mlp_w1; Wt = w1; K = 256;  N = 1024; tile = bidx - 256; }
    else                 { W = mlp_w2; Wt = w2; K = 1024; N = 256;  tile = bidx - 512; }
    int ntx = N >> 5;
    int by = tile / ntx, bx = tile - by * ntx;
    int k0 = by * 32, n0 = bx * 32;
    int tx = threadIdx.x, ty = threadIdx.y;   // 32 x 8
    for (int i = ty; i < 32; i += 8) t[i][tx] = W[(size_t)(k0 + i) * N + n0 + tx];
    __syncthreads();
    for (int i = ty; i < 32; i += 8) Wt[(size_t)(n0 + i) * K + k0 + tx] = __float2half_rn(t[tx][i]);
}

// ---------------- windowed attention (round-7 proven form) ----------------
__global__ __launch_bounds__(256)
void attn_kernel(const __half* __restrict__ qkv,
                 const float* __restrict__ rel_bias,
                 __half* __restrict__ out)
{
    int w    = blockIdx.x;
    int head = blockIdx.y;
    int tid  = threadIdx.x;

    __shared__ float q[NWIN][HD];
    __shared__ float k[NWIN][HD + 1];
    __shared__ float v[NWIN][HD + 1];
    __shared__ float s[NWIN][52];
    __shared__ float bias_s[169];
    __shared__ int   code[NWIN];

    for (int i = tid; i < 169; i += 256)
        bias_s[i] = rel_bias[i * HEADS + head];

    if (tid < NWIN) {
        int wi = w % NWB;
        int wy = wi >> 3, wx = wi & 7;
        int yi = tid / WS, xi = tid % WS;
        int gy = wy * WS + yi, gx = wx * WS + xi;
        int r = (gy < HH - WS ? 0 : (gy < HH - SSH ? 1 : 2)) * 3
              + (gx < WW - WS ? 0 : (gx < WW - SSH ? 1 : 2));
        code[tid] = (yi * 13 + xi) | (r << 16);
    }

    for (int idx = tid; idx < NWIN * (HD / 2); idx += 256) {
        int n = idx >> 4, dp = idx & 15, d = dp * 2;
        size_t base = ((size_t)(w * NWIN + n)) * (3 * CC) + head * HD + d;
        float2 qf = __half22float2(*reinterpret_cast<const __half2*>(qkv + base));
        float2 kf = __half22float2(*reinterpret_cast<const __half2*>(qkv + base + CC));
        float2 vf = __half22float2(*reinterpret_cast<const __half2*>(qkv + base + 2 * CC));
        q[n][d] = qf.x; q[n][d + 1] = qf.y;
        k[n][d] = kf.x; k[n][d + 1] = kf.y;
        v[n][d] = vf.x; v[n][d + 1] = vf.y;
    }
    __syncthreads();

    for (int idx = tid; idx < NWIN * NWIN; idx += 256) {
        int i = idx / NWIN, j = idx % NWIN;
        float dot = 0.0f;
        #pragma unroll
        for (int d = 0; d < HD; d++) dot += q[i][d] * k[j][d];
        int ci = code[i], cj = code[j];
        int rp = (ci & 0xffff) - (cj & 0xffff) + 84;
        float mask = ((ci ^ cj) & 0xffff0000) ? -100.0f : 0.0f;
        s[i][j] = dot * ATT_SCALE + bias_s[rp] + mask;
    }
    __syncthreads();

    int warp = tid >> 5, lane = tid & 31;
    for (int i = warp; i < NWIN; i += 8) {
        float m = -1e30f;
        for (int j = lane; j < NWIN; j += 32) m = fmaxf(m, s[i][j]);
        #pragma unroll
        for (int o = 16; o > 0; o >>= 1) m = fmaxf(m, __shfl_xor_sync(0xffffffff, m, o));
        float sum = 0.0f;
        for (int j = lane; j < NWIN; j += 32) { float e = __expf(s[i][j] - m); s[i][j] = e; sum += e; }
        #pragma unroll
        for (int o = 16; o > 0; o >>= 1) sum += __shfl_xor_sync(0xffffffff, sum, o);
        float inv = 1.0f / sum;
        for (int j = lane; j < NWIN; j += 32) s[i][j] *= inv;
    }
    __syncthreads();

    for (int idx = tid; idx < NWIN * HD; idx += 256) {
        int i = idx >> 5, d = idx & 31;
        float acc = 0.0f;
        #pragma unroll
        for (int j = 0; j < NWIN; j++) acc += s[i][j] * v[j][d];
        out[((size_t)(w * NWIN + i)) * CC + head * HD + d] = __float2half_rn(acc);
    }
}

// ---------------- launcher ----------------
extern "C" void kernel_launch(void* const* d_in, const int* in_sizes, int n_in,
                              void* d_out, int out_size)
{
    (void)in_sizes; (void)n_in; (void)out_size;
    const float* x        = (const float*)d_in[0];
    const float* qkv_w    = (const float*)d_in[1];
    const float* qkv_b    = (const float*)d_in[2];
    const float* proj_w   = (const float*)d_in[3];
    const float* proj_b   = (const float*)d_in[4];
    const float* rel_bias = (const float*)d_in[5];
    const float* ln1_g    = (const float*)d_in[6];
    const float* ln1_b    = (const float*)d_in[7];
    const float* ln2_g    = (const float*)d_in[8];
    const float* ln2_b    = (const float*)d_in[9];
    const float* mlp_w1   = (const float*)d_in[10];
    const float* mlp_b1   = (const float*)d_in[11];
    const float* mlp_w2   = (const float*)d_in[12];
    const float* mlp_b2   = (const float*)d_in[13];
    float* out = (float*)d_out;

    __half *xw, *xn2, *qkvb, *att, *hbuf, *wq, *wp, *w1, *w2;
    float *x1;
    cudaGetSymbolAddress((void**)&xw,   g_xw);
    cudaGetSymbolAddress((void**)&xn2,  g_xn2);
    cudaGetSymbolAddress((void**)&qkvb, g_qkv);
    cudaGetSymbolAddress((void**)&att,  g_att);
    cudaGetSymbolAddress((void**)&x1,   g_x1);
    cudaGetSymbolAddress((void**)&hbuf, g_h);
    cudaGetSymbolAddress((void**)&wq,   g_wq);
    cudaGetSymbolAddress((void**)&wp,   g_wp);
    cudaGetSymbolAddress((void**)&w1,   g_w1);
    cudaGetSymbolAddress((void**)&w2,   g_w2);

    const int SMEM3 = 3 * 2 * 128 * LDKH2 * 2;   // 110592 B (3-stage ring)
    cudaFuncSetAttribute(mma_gemm<0, 256,  768>, cudaFuncAttributeMaxDynamicSharedMemorySize, SMEM3);
    cudaFuncSetAttribute(mma_gemm<1, 256,  256>, cudaFuncAttributeMaxDynamicSharedMemorySize, SMEM3);
    cudaFuncSetAttribute(mma_gemm<2, 256, 1024>, cudaFuncAttributeMaxDynamicSharedMemorySize, SMEM3);
    cudaFuncSetAttribute(mma_gemm<3, 1024, 256>, cudaFuncAttributeMaxDynamicSharedMemorySize, SMEM3);

    // 1. LN1 + shift + window partition -> fp16 xw
    ln_apply_kernel<true><<<TOK / 8, 256>>>(x, ln1_g, ln1_b, xw);
    // 2. all weight transposes in one launch
    transpose_all_kernel<<<768, dim3(32, 8)>>>(qkv_w, proj_w, mlp_w1, mlp_w2, wq, wp, w1, w2);
    // 3. QKV GEMM (half out)
    mma_gemm<0, 256, 768><<<dim3(768 / 128, TOK / 128), 256, SMEM3>>>(xw, wq, qkv_b, qkvb, nullptr);
    // 4. windowed attention (half in/out)
    attn_kernel<<<dim3(NWTOT, HEADS), 256>>>(qkvb, rel_bias, att);
    // 5. proj GEMM + window reverse + roll + residual (float out)
    mma_gemm<1, 256, 256><<<dim3(256 / 128, TOK / 128), 256, SMEM3>>>(att, wp, proj_b, x1, x);
    // 6. LN2 -> fp16 xn2
    ln_apply_kernel<false><<<TOK / 8, 256>>>(x1, ln2_g, ln2_b, xn2);
    // 7. MLP1 + GELU (half out)
    mma_gemm<2, 256, 1024><<<dim3(1024 / 128, TOK / 128), 256, SMEM3>>>(xn2, w1, mlp_b1, hbuf, nullptr);
    // 8. MLP2 + residual -> d_out (float out)
    mma_gemm<3, 1024, 256><<<dim3(256 / 128, TOK / 128), 256, SMEM3>>>(hbuf, w2, mlp_b2, out, x1);
}

// round 12
// speedup vs baseline: 1.3726x; 1.0550x over previous
#include <cuda_runtime.h>
#include <cuda_fp16.h>
#include <math.h>
#include <cstdint>

// ---------------- problem constants ----------------
#define TOK    100352          // 32 * 56 * 56 tokens
#define CC     256
#define HEADS  8
#define HD     32
#define WS     7
#define NWIN   49
#define MLPD   1024
#define HH     56
#define WW     56
#define SSH    3
#define NWB    64
#define NWTOT  2048
#define ATT_SCALE 0.17677669529663687f
#define LN_EPS 1e-5f

// ---------------- scratch (static device globals; no allocation) ----------------
__device__ __half g_xw  [(size_t)TOK * CC];     // LN1+shift output (fp16)
__device__ __half g_xn2 [(size_t)TOK * CC];     // LN2 output (fp16)
__device__ __half g_qkv [(size_t)TOK * 3 * CC];
__device__ __half g_att [(size_t)TOK * CC];
__device__ float  g_x1  [(size_t)TOK * CC];
__device__ __half g_h   [(size_t)TOK * MLPD];
// transposed weights [N,K] row-major, fp16
__device__ __half g_wq [768 * 256];
__device__ __half g_wp [256 * 256];
__device__ __half g_w1 [1024 * 256];
__device__ __half g_w2 [256 * 1024];

// ---------------- helpers ----------------
__device__ __forceinline__ uint32_t smem_u32(const void* p) {
    uint32_t a;
    asm("{ .reg .u64 t; cvta.to.shared.u64 t, %1; cvt.u32.u64 %0, t; }" : "=r"(a) : "l"(p));
    return a;
}
__device__ __forceinline__ void cp_async16(uint32_t dst, const void* src) {
    asm volatile("cp.async.cg.shared.global [%0], [%1], 16;" :: "r"(dst), "l"(src));
}
#define CP_COMMIT() asm volatile("cp.async.commit_group;" ::: "memory")

// m16n8k16 fp16 MMA, fp32 accumulate
__device__ __forceinline__ void mma_f16(float* c,
                                        uint32_t a0, uint32_t a1, uint32_t a2, uint32_t a3,
                                        uint32_t b0, uint32_t b1) {
    asm volatile(
        "mma.sync.aligned.m16n8k16.row.col.f32.f16.f16.f32 "
        "{%0,%1,%2,%3}, {%4,%5,%6,%7}, {%8,%9}, {%0,%1,%2,%3};"
        : "+f"(c[0]), "+f"(c[1]), "+f"(c[2]), "+f"(c[3])
        : "r"(a0), "r"(a1), "r"(a2), "r"(a3), "r"(b0), "r"(b1));
}

#define LDKH2 72   // padded row stride (halves) for 64-half chunks

// scalar-LDS K-step MMA over 64-half chunk (proven form)
__device__ __forceinline__ void chunk_mma64(const __half* As, const __half* Bs,
                                            int wm, int wn, int g, int t4,
                                            float acc[4][4][4]) {
    #pragma unroll
    for (int ks = 0; ks < 4; ks++) {
        const int kb = ks * 16;
        uint32_t bf[4][2];
        #pragma unroll
        for (int ni = 0; ni < 4; ni++) {
            const __half* bp = Bs + (wn + ni * 8 + g) * LDKH2 + kb + t4 * 2;
            bf[ni][0] = *reinterpret_cast<const uint32_t*>(bp);
            bf[ni][1] = *reinterpret_cast<const uint32_t*>(bp + 8);
        }
        #pragma unroll
        for (int mi = 0; mi < 4; mi++) {
            const __half* ap = As + (wm + mi * 16 + g) * LDKH2 + kb + t4 * 2;
            uint32_t a0 = *reinterpret_cast<const uint32_t*>(ap);
            uint32_t a1 = *reinterpret_cast<const uint32_t*>(ap + 8 * LDKH2);
            uint32_t a2 = *reinterpret_cast<const uint32_t*>(ap + 8);
            uint32_t a3 = *reinterpret_cast<const uint32_t*>(ap + 8 * LDKH2 + 8);
            #pragma unroll
            for (int ni = 0; ni < 4; ni++)
                mma_f16(acc[mi][ni], a0, a1, a2, a3, bf[ni][0], bf[ni][1]);
        }
    }
}

// shared epilogue. MODE 0: half out (QKV)  MODE 1: float res+scatter (proj)
// MODE 2: half gelu out (MLP1)  MODE 3: float res out (MLP2)
template<int MODE, int NDIM>
__device__ __forceinline__ void gemm_epilogue(float acc[4][4][4],
                                              int m0, int n0, int wm, int wn, int g, int t4,
                                              const float* __restrict__ bias,
                                              void* __restrict__ OutV,
                                              const float* __restrict__ res) {
    #pragma unroll
    for (int mi = 0; mi < 4; mi++) {
        #pragma unroll
        for (int h = 0; h < 2; h++) {
            int m = m0 + wm + mi * 16 + g + h * 8;
            size_t drow;
            if (MODE == 1) {
                int w = m / NWIN, ntok = m % NWIN;
                int bb2 = w / NWB, wi = w % NWB;
                int wy = wi >> 3, wx = wi & 7;
                int hy = wy * WS + ntok / WS, hx = wx * WS + ntok % WS;
                int oy = (hy + SSH) % HH, ox = (hx + SSH) % WW;
                drow = ((size_t)bb2 * HH * WW + oy * WW + ox) * CC;
            } else {
                drow = (size_t)m * NDIM;
            }
            #pragma unroll
            for (int ni = 0; ni < 4; ni++) {
                int n = n0 + wn + ni * 8 + 2 * t4;
                float2 bv = *reinterpret_cast<const float2*>(bias + n);
                float vx = acc[mi][ni][2 * h + 0] + bv.x;
                float vy = acc[mi][ni][2 * h + 1] + bv.y;
                if (MODE == 1 || MODE == 3) {
                    float2 r = *reinterpret_cast<const float2*>(res + drow + n);
                    float2 o = { vx + r.x, vy + r.y };
                    *reinterpret_cast<float2*>((float*)OutV + drow + n) = o;
                } else {
                    if (MODE == 2) {
                        vx = 0.5f * vx * (1.0f + erff(vx * 0.70710678118654752f));
                        vy = 0.5f * vy * (1.0f + erff(vy * 0.70710678118654752f));
                    }
                    *reinterpret_cast<__half2*>((__half*)OutV + drow + n) =
                        __floats2half2_rn(vx, vy);
                }
            }
        }
    }
}

// ---------------- cp.async fp16 GEMM, 64-half K chunks, 3-stage ring ----------------
template<int MODE, int KDIM, int NDIM>
__global__ __launch_bounds__(256)
void mma_gemm(const __half* __restrict__ A, const __half* __restrict__ Wt,
              const float* __restrict__ bias, void* __restrict__ Out,
              const float* __restrict__ res)
{
    extern __shared__ char smraw[];
    __half* sm = reinterpret_cast<__half*>(smraw);
    const uint32_t sbase = smem_u32(smraw);

    const int tid  = threadIdx.x;
    const int wid  = tid >> 5, lane = tid & 31;
    const int g    = lane >> 2, t4 = lane & 3;
    const int wm   = (wid & 1) * 64;
    const int wn   = (wid >> 1) * 32;
    const int m0   = blockIdx.y * 128;
    const int n0   = blockIdx.x * 128;

    constexpr int NC = KDIM / 64;
    constexpr int STAGE = 2 * 128 * LDKH2;          // halves per stage (A+B)

    auto load_chunk = [&](int c, int s) {
        const int k0 = c * 64;
        uint32_t sa  = sbase + (uint32_t)(s * STAGE) * 2u;
        uint32_t sb2 = sa + 128u * LDKH2 * 2u;
        #pragma unroll
        for (int t = 0; t < 4; t++) {
            int f = t * 256 + tid;
            int row = f >> 3, seg = f & 7;
            cp_async16(sa  + (uint32_t)(row * LDKH2) * 2u + seg * 16,
                       A  + (size_t)(m0 + row) * KDIM + k0 + seg * 8);
            cp_async16(sb2 + (uint32_t)(row * LDKH2) * 2u + seg * 16,
                       Wt + (size_t)(n0 + row) * KDIM + k0 + seg * 8);
        }
        CP_COMMIT();
    };

    float acc[4][4][4];
    #pragma unroll
    for (int i = 0; i < 4; i++)
        #pragma unroll
        for (int j = 0; j < 4; j++)
            #pragma unroll
            for (int e = 0; e < 4; e++) acc[i][j][e] = 0.0f;

    load_chunk(0, 0);
    load_chunk(1, 1);

    int stage = 0;
    for (int c = 0; c < NC; c++) {
        if (c + 1 < NC) asm volatile("cp.async.wait_group 1;" ::: "memory");
        else            asm volatile("cp.async.wait_group 0;" ::: "memory");
        __syncthreads();
        if (c + 2 < NC) {
            int s2 = stage + 2; if (s2 >= 3) s2 -= 3;
            load_chunk(c + 2, s2);
        }
        const __half* As = sm + stage * STAGE;
        const __half* Bs = As + 128 * LDKH2;
        chunk_mma64(As, Bs, wm, wn, g, t4, acc);
        if (++stage == 3) stage = 0;
    }
    gemm_epilogue<MODE, NDIM>(acc, m0, n0, wm, wn, g, t4, bias, Out, res);
}

// ---------------- fused LN apply: warp/token, stats + normalize -> fp16 ----------------
template<bool SHIFT>
__global__ __launch_bounds__(256)
void ln_apply_kernel(const float* __restrict__ x,
                     const float* __restrict__ g,
                     const float* __restrict__ b,
                     __half* __restrict__ out)
{
    int t = blockIdx.x * 8 + (threadIdx.x >> 5);
    int lane = threadIdx.x & 31;

    int src;
    if (SHIFT) {
        int w = t / NWIN, n = t % NWIN;
        int bb = w >> 6, wi = w & 63;
        int wy = wi >> 3, wx = wi & 7;
        int hy = wy * WS + n / WS, hx = wx * WS + n % WS;
        int sy = hy + SSH; if (sy >= HH) sy -= HH;
        int sx = hx + SSH; if (sx >= WW) sx -= WW;
        src = bb * (HH * WW) + sy * WW + sx;
    } else {
        src = t;
    }

    const float4* rp = reinterpret_cast<const float4*>(x + (size_t)src * CC);
    float4 a = rp[lane], c = rp[lane + 32];
    float s  = a.x + a.y + a.z + a.w + c.x + c.y + c.z + c.w;
    float s2 = a.x * a.x + a.y * a.y + a.z * a.z + a.w * a.w
             + c.x * c.x + c.y * c.y + c.z * c.z + c.w * c.w;
    #pragma unroll
    for (int o = 16; o > 0; o >>= 1) {
        s  += __shfl_xor_sync(0xffffffff, s, o);
        s2 += __shfl_xor_sync(0xffffffff, s2, o);
    }
    float mu  = s * (1.0f / CC);
    float var = s2 * (1.0f / CC) - mu * mu;
    float inv = rsqrtf(var + LN_EPS);

    const float4* gp = reinterpret_cast<const float4*>(g);
    const float4* bp = reinterpret_cast<const float4*>(b);
    uint2* op = reinterpret_cast<uint2*>(out + (size_t)t * CC);
    #pragma unroll
    for (int h = 0; h < 2; h++) {
        float4 v = h ? c : a;
        float4 gg = gp[lane + h * 32], bb4 = bp[lane + h * 32];
        __half2 h01 = __floats2half2_rn((v.x - mu) * inv * gg.x + bb4.x,
                                        (v.y - mu) * inv * gg.y + bb4.y);
        __half2 h23 = __floats2half2_rn((v.z - mu) * inv * gg.z + bb4.z,
                                        (v.w - mu) * inv * gg.w + bb4.w);
        uint2 pk = { *reinterpret_cast<uint32_t*>(&h01), *reinterpret_cast<uint32_t*>(&h23) };
        op[lane + h * 32] = pk;
    }
}

// ---------------- merged weight transpose (all 4 weights in one launch) ----------------
__global__ void transpose_all_kernel(const float* __restrict__ qkv_w,
                                     const float* __restrict__ proj_w,
                                     const float* __restrict__ mlp_w1,
                                     const float* __restrict__ mlp_w2,
                                     __half* __restrict__ wq, __half* __restrict__ wp,
                                     __half* __restrict__ w1, __half* __restrict__ w2)
{
    __shared__ float t[32][33];
    int bidx = blockIdx.x;
    const float* W; __half* Wt; int K, N, tile;
    if (bidx < 192)      { W = qkv_w;  Wt = wq; K = 256;  N = 768;  tile = bidx; }
    else if (bidx < 256) { W = proj_w; Wt = wp; K = 256;  N = 256;  tile = bidx - 192; }
    else if (bidx < 512) { W = mlp_w1; Wt = w1; K = 256;  N = 1024; tile = bidx - 256; }
    else                 { W = mlp_w2; Wt = w2; K = 1024; N = 256;  tile = bidx - 512; }
    int ntx = N >> 5;
    int by = tile / ntx, bx = tile - by * ntx;
    int k0 = by * 32, n0 = bx * 32;
    int tx = threadIdx.x, ty = threadIdx.y;   // 32 x 8
    for (int i = ty; i < 32; i += 8) t[i][tx] = W[(size_t)(k0 + i) * N + n0 + tx];
    __syncthreads();
    for (int i = ty; i < 32; i += 8) Wt[(size_t)(n0 + i) * K + k0 + tx] = __float2half_rn(t[tx][i]);
}

// ---------------- windowed attention: half2-resident q/k/v (LDS traffic halved) ----------------
#define QKLD 17   // row stride in 32-bit words (16 data + 1 pad; 17 coprime 32)
__global__ __launch_bounds__(256)
void attn_kernel(const __half* __restrict__ qkv,
                 const float* __restrict__ rel_bias,
                 __half* __restrict__ out)
{
    int w    = blockIdx.x;
    int head = blockIdx.y;
    int tid  = threadIdx.x;

    __shared__ uint32_t q[NWIN][QKLD];   // half2 words
    __shared__ uint32_t k[NWIN][QKLD];
    __shared__ uint32_t v[NWIN][QKLD];
    __shared__ float s[NWIN][52];
    __shared__ float bias_s[169];
    __shared__ int   code[NWIN];

    for (int i = tid; i < 169; i += 256)
        bias_s[i] = rel_bias[i * HEADS + head];

    if (tid < NWIN) {
        int wi = w % NWB;
        int wy = wi >> 3, wx = wi & 7;
        int yi = tid / WS, xi = tid % WS;
        int gy = wy * WS + yi, gx = wx * WS + xi;
        int r = (gy < HH - WS ? 0 : (gy < HH - SSH ? 1 : 2)) * 3
              + (gx < WW - WS ? 0 : (gx < WW - SSH ? 1 : 2));
        code[tid] = (yi * 13 + xi) | (r << 16);
    }

    // copy q/k/v rows as raw half2 words (no conversion)
    for (int idx = tid; idx < NWIN * 16; idx += 256) {
        int n = idx >> 4, wd = idx & 15;
        size_t base = ((size_t)(w * NWIN + n)) * (3 * CC) + head * HD + wd * 2;
        q[n][wd] = *reinterpret_cast<const uint32_t*>(qkv + base);
        k[n][wd] = *reinterpret_cast<const uint32_t*>(qkv + base + CC);
        v[n][wd] = *reinterpret_cast<const uint32_t*>(qkv + base + 2 * CC);
    }
    __syncthreads();

    // score: per pair, q reads are broadcast, k reads 16 LDS.32 (conflict-free, stride 17)
    for (int idx = tid; idx < NWIN * NWIN; idx += 256) {
        int i = idx / NWIN, j = idx % NWIN;
        float dot = 0.0f;
        #pragma unroll
        for (int wd = 0; wd < 16; wd++) {
            float2 qf = __half22float2(*reinterpret_cast<const __half2*>(&q[i][wd]));
            float2 kf = __half22float2(*reinterpret_cast<const __half2*>(&k[j][wd]));
            dot += qf.x * kf.x + qf.y * kf.y;
        }
        int ci = code[i], cj = code[j];
        int rp = (ci & 0xffff) - (cj & 0xffff) + 84;
        float mask = ((ci ^ cj) & 0xffff0000) ? -100.0f : 0.0f;
        s[i][j] = dot * ATT_SCALE + bias_s[rp] + mask;
    }
    __syncthreads();

    // softmax: warp per row
    int warp = tid >> 5, lane = tid & 31;
    for (int i = warp; i < NWIN; i += 8) {
        float m = -1e30f;
        for (int j = lane; j < NWIN; j += 32) m = fmaxf(m, s[i][j]);
        #pragma unroll
        for (int o = 16; o > 0; o >>= 1) m = fmaxf(m, __shfl_xor_sync(0xffffffff, m, o));
        float sum = 0.0f;
        for (int j = lane; j < NWIN; j += 32) { float e = __expf(s[i][j] - m); s[i][j] = e; sum += e; }
        #pragma unroll
        for (int o = 16; o > 0; o >>= 1) sum += __shfl_xor_sync(0xffffffff, sum, o);
        float inv = 1.0f / sum;
        for (int j = lane; j < NWIN; j += 32) s[i][j] *= inv;
    }
    __syncthreads();

    // PV: warp per row i; lane owns column d; v word shared by lane pairs (broadcast)
    for (int i = warp; i < NWIN; i += 8) {
        float acc = 0.0f;
        int wsel = lane >> 1, hsel = lane & 1;
        #pragma unroll
        for (int j = 0; j < NWIN; j++) {
            float sv = s[i][j];
            __half2 vh = *reinterpret_cast<const __half2*>(&v[j][wsel]);
            float ve = hsel ? __high2float(vh) : __low2float(vh);
            acc += sv * ve;
        }
        out[((size_t)(w * NWIN + i)) * CC + head * HD + lane] = __float2half_rn(acc);
    }
}

// ---------------- launcher ----------------
extern "C" void kernel_launch(void* const* d_in, const int* in_sizes, int n_in,
                              void* d_out, int out_size)
{
    (void)in_sizes; (void)n_in; (void)out_size;
    const float* x        = (const float*)d_in[0];
    const float* qkv_w    = (const float*)d_in[1];
    const float* qkv_b    = (const float*)d_in[2];
    const float* proj_w   = (const float*)d_in[3];
    const float* proj_b   = (const float*)d_in[4];
    const float* rel_bias = (const float*)d_in[5];
    const float* ln1_g    = (const float*)d_in[6];
    const float* ln1_b    = (const float*)d_in[7];
    const float* ln2_g    = (const float*)d_in[8];
    const float* ln2_b    = (const float*)d_in[9];
    const float* mlp_w1   = (const float*)d_in[10];
    const float* mlp_b1   = (const float*)d_in[11];
    const float* mlp_w2   = (const float*)d_in[12];
    const float* mlp_b2   = (const float*)d_in[13];
    float* out = (float*)d_out;

    __half *xw, *xn2, *qkvb, *att, *hbuf, *wq, *wp, *w1, *w2;
    float *x1;
    cudaGetSymbolAddress((void**)&xw,   g_xw);
    cudaGetSymbolAddress((void**)&xn2,  g_xn2);
    cudaGetSymbolAddress((void**)&qkvb, g_qkv);
    cudaGetSymbolAddress((void**)&att,  g_att);
    cudaGetSymbolAddress((void**)&x1,   g_x1);
    cudaGetSymbolAddress((void**)&hbuf, g_h);
    cudaGetSymbolAddress((void**)&wq,   g_wq);
    cudaGetSymbolAddress((void**)&wp,   g_wp);
    cudaGetSymbolAddress((void**)&w1,   g_w1);
    cudaGetSymbolAddress((void**)&w2,   g_w2);

    const int SMEM3 = 3 * 2 * 128 * LDKH2 * 2;   // 110592 B (3-stage ring)
    cudaFuncSetAttribute(mma_gemm<0, 256,  768>, cudaFuncAttributeMaxDynamicSharedMemorySize, SMEM3);
    cudaFuncSetAttribute(mma_gemm<1, 256,  256>, cudaFuncAttributeMaxDynamicSharedMemorySize, SMEM3);
    cudaFuncSetAttribute(mma_gemm<2, 256, 1024>, cudaFuncAttributeMaxDynamicSharedMemorySize, SMEM3);
    cudaFuncSetAttribute(mma_gemm<3, 1024, 256>, cudaFuncAttributeMaxDynamicSharedMemorySize, SMEM3);

    // 1. LN1 + shift + window partition -> fp16 xw
    ln_apply_kernel<true><<<TOK / 8, 256>>>(x, ln1_g, ln1_b, xw);
    // 2. all weight transposes in one launch
    transpose_all_kernel<<<768, dim3(32, 8)>>>(qkv_w, proj_w, mlp_w1, mlp_w2, wq, wp, w1, w2);
    // 3. QKV GEMM (half out)
    mma_gemm<0, 256, 768><<<dim3(768 / 128, TOK / 128), 256, SMEM3>>>(xw, wq, qkv_b, qkvb, nullptr);
    // 4. windowed attention (half in/out)
    attn_kernel<<<dim3(NWTOT, HEADS), 256>>>(qkvb, rel_bias, att);
    // 5. proj GEMM + window reverse + roll + residual (float out)
    mma_gemm<1, 256, 256><<<dim3(256 / 128, TOK / 128), 256, SMEM3>>>(att, wp, proj_b, x1, x);
    // 6. LN2 -> fp16 xn2
    ln_apply_kernel<false><<<TOK / 8, 256>>>(x1, ln2_g, ln2_b, xn2);
    // 7. MLP1 + GELU (half out)
    mma_gemm<2, 256, 1024><<<dim3(1024 / 128, TOK / 128), 256, SMEM3>>>(xn2, w1, mlp_b1, hbuf, nullptr);
    // 8. MLP2 + residual -> d_out (float out)
    mma_gemm<3, 1024, 256><<<dim3(256 / 128, TOK / 128), 256, SMEM3>>>(hbuf, w2, mlp_b2, out, x1);
}

// round 13
// speedup vs baseline: 1.5349x; 1.1182x over previous
#include <cuda_runtime.h>
#include <cuda_fp16.h>
#include <math.h>
#include <cstdint>

// ---------------- problem constants ----------------
#define TOK    100352          // 32 * 56 * 56 tokens
#define CC     256
#define HEADS  8
#define HD     32
#define WS     7
#define NWIN   49
#define MLPD   1024
#define HH     56
#define WW     56
#define SSH    3
#define NWB    64
#define NWTOT  2048
#define ATT_SCALE 0.17677669529663687f
#define LN_EPS 1e-5f

// ---------------- scratch (static device globals; no allocation) ----------------
__device__ __half g_xw  [(size_t)TOK * CC];     // LN1+shift output (fp16)
__device__ __half g_xn2 [(size_t)TOK * CC];     // LN2 output (fp16)
__device__ __half g_qkv [(size_t)TOK * 3 * CC];
__device__ __half g_att [(size_t)TOK * CC];
__device__ float  g_x1  [(size_t)TOK * CC];
__device__ __half g_h   [(size_t)TOK * MLPD];
// transposed weights [N,K] row-major, fp16
__device__ __half g_wq [768 * 256];
__device__ __half g_wp [256 * 256];
__device__ __half g_w1 [1024 * 256];
__device__ __half g_w2 [256 * 1024];

// ---------------- helpers ----------------
__device__ __forceinline__ uint32_t smem_u32(const void* p) {
    uint32_t a;
    asm("{ .reg .u64 t; cvta.to.shared.u64 t, %1; cvt.u32.u64 %0, t; }" : "=r"(a) : "l"(p));
    return a;
}
__device__ __forceinline__ void cp_async16(uint32_t dst, const void* src) {
    asm volatile("cp.async.cg.shared.global [%0], [%1], 16;" :: "r"(dst), "l"(src));
}
#define CP_COMMIT() asm volatile("cp.async.commit_group;" ::: "memory")

// m16n8k16 fp16 MMA, fp32 accumulate
__device__ __forceinline__ void mma_f16(float* c,
                                        uint32_t a0, uint32_t a1, uint32_t a2, uint32_t a3,
                                        uint32_t b0, uint32_t b1) {
    asm volatile(
        "mma.sync.aligned.m16n8k16.row.col.f32.f16.f16.f32 "
        "{%0,%1,%2,%3}, {%4,%5,%6,%7}, {%8,%9}, {%0,%1,%2,%3};"
        : "+f"(c[0]), "+f"(c[1]), "+f"(c[2]), "+f"(c[3])
        : "r"(a0), "r"(a1), "r"(a2), "r"(a3), "r"(b0), "r"(b1));
}
__device__ __forceinline__ void ldsm_x4(uint32_t addr, uint32_t& r0, uint32_t& r1,
                                        uint32_t& r2, uint32_t& r3) {
    asm volatile("ldmatrix.sync.aligned.m8n8.x4.shared.b16 {%0,%1,%2,%3}, [%4];"
                 : "=r"(r0), "=r"(r1), "=r"(r2), "=r"(r3) : "r"(addr));
}

#define LDKH2 72   // padded row stride (halves) for 64-half chunks

// scalar-LDS K-step MMA over 64-half chunk (proven form)
__device__ __forceinline__ void chunk_mma64(const __half* As, const __half* Bs,
                                            int wm, int wn, int g, int t4,
                                            float acc[4][4][4]) {
    #pragma unroll
    for (int ks = 0; ks < 4; ks++) {
        const int kb = ks * 16;
        uint32_t bf[4][2];
        #pragma unroll
        for (int ni = 0; ni < 4; ni++) {
            const __half* bp = Bs + (wn + ni * 8 + g) * LDKH2 + kb + t4 * 2;
            bf[ni][0] = *reinterpret_cast<const uint32_t*>(bp);
            bf[ni][1] = *reinterpret_cast<const uint32_t*>(bp + 8);
        }
        #pragma unroll
        for (int mi = 0; mi < 4; mi++) {
            const __half* ap = As + (wm + mi * 16 + g) * LDKH2 + kb + t4 * 2;
            uint32_t a0 = *reinterpret_cast<const uint32_t*>(ap);
            uint32_t a1 = *reinterpret_cast<const uint32_t*>(ap + 8 * LDKH2);
            uint32_t a2 = *reinterpret_cast<const uint32_t*>(ap + 8);
            uint32_t a3 = *reinterpret_cast<const uint32_t*>(ap + 8 * LDKH2 + 8);
            #pragma unroll
            for (int ni = 0; ni < 4; ni++)
                mma_f16(acc[mi][ni], a0, a1, a2, a3, bf[ni][0], bf[ni][1]);
        }
    }
}

// shared epilogue. MODE 0: half out (QKV)  MODE 1: float res+scatter (proj)
// MODE 2: half gelu out (MLP1)  MODE 3: float res out (MLP2)
template<int MODE, int NDIM>
__device__ __forceinline__ void gemm_epilogue(float acc[4][4][4],
                                              int m0, int n0, int wm, int wn, int g, int t4,
                                              const float* __restrict__ bias,
                                              void* __restrict__ OutV,
                                              const float* __restrict__ res) {
    #pragma unroll
    for (int mi = 0; mi < 4; mi++) {
        #pragma unroll
        for (int h = 0; h < 2; h++) {
            int m = m0 + wm + mi * 16 + g + h * 8;
            size_t drow;
            if (MODE == 1) {
                int w = m / NWIN, ntok = m % NWIN;
                int bb2 = w / NWB, wi = w % NWB;
                int wy = wi >> 3, wx = wi & 7;
                int hy = wy * WS + ntok / WS, hx = wx * WS + ntok % WS;
                int oy = (hy + SSH) % HH, ox = (hx + SSH) % WW;
                drow = ((size_t)bb2 * HH * WW + oy * WW + ox) * CC;
            } else {
                drow = (size_t)m * NDIM;
            }
            #pragma unroll
            for (int ni = 0; ni < 4; ni++) {
                int n = n0 + wn + ni * 8 + 2 * t4;
                float2 bv = *reinterpret_cast<const float2*>(bias + n);
                float vx = acc[mi][ni][2 * h + 0] + bv.x;
                float vy = acc[mi][ni][2 * h + 1] + bv.y;
                if (MODE == 1 || MODE == 3) {
                    float2 r = *reinterpret_cast<const float2*>(res + drow + n);
                    float2 o = { vx + r.x, vy + r.y };
                    *reinterpret_cast<float2*>((float*)OutV + drow + n) = o;
                } else {
                    if (MODE == 2) {
                        vx = 0.5f * vx * (1.0f + erff(vx * 0.70710678118654752f));
                        vy = 0.5f * vy * (1.0f + erff(vy * 0.70710678118654752f));
                    }
                    *reinterpret_cast<__half2*>((__half*)OutV + drow + n) =
                        __floats2half2_rn(vx, vy);
                }
            }
        }
    }
}

// ---------------- cp.async fp16 GEMM, 64-half K chunks, 3-stage ring ----------------
template<int MODE, int KDIM, int NDIM>
__global__ __launch_bounds__(256)
void mma_gemm(const __half* __restrict__ A, const __half* __restrict__ Wt,
              const float* __restrict__ bias, void* __restrict__ Out,
              const float* __restrict__ res)
{
    extern __shared__ char smraw[];
    __half* sm = reinterpret_cast<__half*>(smraw);
    const uint32_t sbase = smem_u32(smraw);

    const int tid  = threadIdx.x;
    const int wid  = tid >> 5, lane = tid & 31;
    const int g    = lane >> 2, t4 = lane & 3;
    const int wm   = (wid & 1) * 64;
    const int wn   = (wid >> 1) * 32;
    const int m0   = blockIdx.y * 128;
    const int n0   = blockIdx.x * 128;

    constexpr int NC = KDIM / 64;
    constexpr int STAGE = 2 * 128 * LDKH2;          // halves per stage (A+B)

    auto load_chunk = [&](int c, int s) {
        const int k0 = c * 64;
        uint32_t sa  = sbase + (uint32_t)(s * STAGE) * 2u;
        uint32_t sb2 = sa + 128u * LDKH2 * 2u;
        #pragma unroll
        for (int t = 0; t < 4; t++) {
            int f = t * 256 + tid;
            int row = f >> 3, seg = f & 7;
            cp_async16(sa  + (uint32_t)(row * LDKH2) * 2u + seg * 16,
                       A  + (size_t)(m0 + row) * KDIM + k0 + seg * 8);
            cp_async16(sb2 + (uint32_t)(row * LDKH2) * 2u + seg * 16,
                       Wt + (size_t)(n0 + row) * KDIM + k0 + seg * 8);
        }
        CP_COMMIT();
    };

    float acc[4][4][4];
    #pragma unroll
    for (int i = 0; i < 4; i++)
        #pragma unroll
        for (int j = 0; j < 4; j++)
            #pragma unroll
            for (int e = 0; e < 4; e++) acc[i][j][e] = 0.0f;

    load_chunk(0, 0);
    load_chunk(1, 1);

    int stage = 0;
    for (int c = 0; c < NC; c++) {
        if (c + 1 < NC) asm volatile("cp.async.wait_group 1;" ::: "memory");
        else            asm volatile("cp.async.wait_group 0;" ::: "memory");
        __syncthreads();
        if (c + 2 < NC) {
            int s2 = stage + 2; if (s2 >= 3) s2 -= 3;
            load_chunk(c + 2, s2);
        }
        const __half* As = sm + stage * STAGE;
        const __half* Bs = As + 128 * LDKH2;
        chunk_mma64(As, Bs, wm, wn, g, t4, acc);
        if (++stage == 3) stage = 0;
    }
    gemm_epilogue<MODE, NDIM>(acc, m0, n0, wm, wn, g, t4, bias, Out, res);
}

// ---------------- fused LN apply: warp/token, stats + normalize -> fp16 ----------------
template<bool SHIFT>
__global__ __launch_bounds__(256)
void ln_apply_kernel(const float* __restrict__ x,
                     const float* __restrict__ g,
                     const float* __restrict__ b,
                     __half* __restrict__ out)
{
    int t = blockIdx.x * 8 + (threadIdx.x >> 5);
    int lane = threadIdx.x & 31;

    int src;
    if (SHIFT) {
        int w = t / NWIN, n = t % NWIN;
        int bb = w >> 6, wi = w & 63;
        int wy = wi >> 3, wx = wi & 7;
        int hy = wy * WS + n / WS, hx = wx * WS + n % WS;
        int sy = hy + SSH; if (sy >= HH) sy -= HH;
        int sx = hx + SSH; if (sx >= WW) sx -= WW;
        src = bb * (HH * WW) + sy * WW + sx;
    } else {
        src = t;
    }

    const float4* rp = reinterpret_cast<const float4*>(x + (size_t)src * CC);
    float4 a = rp[lane], c = rp[lane + 32];
    float s  = a.x + a.y + a.z + a.w + c.x + c.y + c.z + c.w;
    float s2 = a.x * a.x + a.y * a.y + a.z * a.z + a.w * a.w
             + c.x * c.x + c.y * c.y + c.z * c.z + c.w * c.w;
    #pragma unroll
    for (int o = 16; o > 0; o >>= 1) {
        s  += __shfl_xor_sync(0xffffffff, s, o);
        s2 += __shfl_xor_sync(0xffffffff, s2, o);
    }
    float mu  = s * (1.0f / CC);
    float var = s2 * (1.0f / CC) - mu * mu;
    float inv = rsqrtf(var + LN_EPS);

    const float4* gp = reinterpret_cast<const float4*>(g);
    const float4* bp = reinterpret_cast<const float4*>(b);
    uint2* op = reinterpret_cast<uint2*>(out + (size_t)t * CC);
    #pragma unroll
    for (int h = 0; h < 2; h++) {
        float4 v = h ? c : a;
        float4 gg = gp[lane + h * 32], bb4 = bp[lane + h * 32];
        __half2 h01 = __floats2half2_rn((v.x - mu) * inv * gg.x + bb4.x,
                                        (v.y - mu) * inv * gg.y + bb4.y);
        __half2 h23 = __floats2half2_rn((v.z - mu) * inv * gg.z + bb4.z,
                                        (v.w - mu) * inv * gg.w + bb4.w);
        uint2 pk = { *reinterpret_cast<uint32_t*>(&h01), *reinterpret_cast<uint32_t*>(&h23) };
        op[lane + h * 32] = pk;
    }
}

// ---------------- merged weight transpose (all 4 weights in one launch) ----------------
__global__ void transpose_all_kernel(const float* __restrict__ qkv_w,
                                     const float* __restrict__ proj_w,
                                     const float* __restrict__ mlp_w1,
                                     const float* __restrict__ mlp_w2,
                                     __half* __restrict__ wq, __half* __restrict__ wp,
                                     __half* __restrict__ w1, __half* __restrict__ w2)
{
    __shared__ float t[32][33];
    int bidx = blockIdx.x;
    const float* W; __half* Wt; int K, N, tile;
    if (bidx < 192)      { W = qkv_w;  Wt = wq; K = 256;  N = 768;  tile = bidx; }
    else if (bidx < 256) { W = proj_w; Wt = wp; K = 256;  N = 256;  tile = bidx - 192; }
    else if (bidx < 512) { W = mlp_w1; Wt = w1; K = 256;  N = 1024; tile = bidx - 256; }
    else                 { W = mlp_w2; Wt = w2; K = 1024; N = 256;  tile = bidx - 512; }
    int ntx = N >> 5;
    int by = tile / ntx, bx = tile - by * ntx;
    int k0 = by * 32, n0 = bx * 32;
    int tx = threadIdx.x, ty = threadIdx.y;   // 32 x 8
    for (int i = ty; i < 32; i += 8) t[i][tx] = W[(size_t)(k0 + i) * N + n0 + tx];
    __syncthreads();
    for (int i = ty; i < 32; i += 8) Wt[(size_t)(n0 + i) * K + k0 + tx] = __float2half_rn(t[tx][i]);
}

// ---------------- windowed attention: HMMA score + scalar softmax/PV ----------------
#define LDQ  40   // halves per q/k row (stride 20 words -> conflict-free ldmatrix)
#define QKLD 17   // v row stride in 32-bit words
__global__ __launch_bounds__(256)
void attn_kernel(const __half* __restrict__ qkv,
                 const float* __restrict__ rel_bias,
                 __half* __restrict__ out)
{
    int w    = blockIdx.x;
    int head = blockIdx.y;
    int tid  = threadIdx.x;

    __shared__ __half qs[64 * LDQ];     // rows 49..63 garbage, outputs guarded
    __shared__ __half ksm[64 * LDQ];
    __shared__ uint32_t v[NWIN][QKLD];  // half2 words
    __shared__ float s[NWIN][52];
    __shared__ float bias_s[169];
    __shared__ int   code[NWIN];

    for (int i = tid; i < 169; i += 256)
        bias_s[i] = rel_bias[i * HEADS + head];

    if (tid < NWIN) {
        int wi = w % NWB;
        int wy = wi >> 3, wx = wi & 7;
        int yi = tid / WS, xi = tid % WS;
        int gy = wy * WS + yi, gx = wx * WS + xi;
        int r = (gy < HH - WS ? 0 : (gy < HH - SSH ? 1 : 2)) * 3
              + (gx < WW - WS ? 0 : (gx < WW - SSH ? 1 : 2));
        code[tid] = (yi * 13 + xi) | (r << 16);
    }

    // copy q/k/v rows as raw half2 words
    for (int idx = tid; idx < NWIN * 16; idx += 256) {
        int n = idx >> 4, wd = idx & 15;
        size_t base = ((size_t)(w * NWIN + n)) * (3 * CC) + head * HD + wd * 2;
        *reinterpret_cast<uint32_t*>(&qs[n * LDQ + wd * 2])  = *reinterpret_cast<const uint32_t*>(qkv + base);
        *reinterpret_cast<uint32_t*>(&ksm[n * LDQ + wd * 2]) = *reinterpret_cast<const uint32_t*>(qkv + base + CC);
        v[n][wd] = *reinterpret_cast<const uint32_t*>(qkv + base + 2 * CC);
    }
    __syncthreads();

    // ---- score via HMMA: 64x64x32 padded, 8 warps x (16m x 32n) tiles ----
    {
        const int wid = tid >> 5, lane = tid & 31;
        const int g = lane >> 2, t4 = lane & 3;
        const int mi = (wid & 3) * 16;
        const int nb = (wid >> 2) * 32;
        const int lr = lane & 7, lt8 = (lane >> 3) & 1, lt16 = lane >> 4;
        const uint32_t qbase = smem_u32(qs);
        const uint32_t kbase = smem_u32(ksm);

        float acc[4][4];
        #pragma unroll
        for (int a = 0; a < 4; a++)
            #pragma unroll
            for (int e = 0; e < 4; e++) acc[a][e] = 0.0f;

        #pragma unroll
        for (int kstep = 0; kstep < 2; kstep++) {
            const int kb = kstep * 16;
            uint32_t bf[4][2];
            #pragma unroll
            for (int np = 0; np < 2; np++) {
                uint32_t addr = kbase + (uint32_t)(((nb + np * 16 + lt16 * 8 + lr) * LDQ
                                                    + kb + lt8 * 8) * 2);
                ldsm_x4(addr, bf[2 * np][0], bf[2 * np][1], bf[2 * np + 1][0], bf[2 * np + 1][1]);
            }
            uint32_t aaddr = qbase + (uint32_t)(((mi + lt8 * 8 + lr) * LDQ + kb + lt16 * 8) * 2);
            uint32_t a0, a1, a2, a3;
            ldsm_x4(aaddr, a0, a1, a2, a3);
            #pragma unroll
            for (int ni = 0; ni < 4; ni++)
                mma_f16(acc[ni], a0, a1, a2, a3, bf[ni][0], bf[ni][1]);
        }

        // epilogue: guarded writes, bias + shift mask
        #pragma unroll
        for (int h = 0; h < 2; h++) {
            int i = mi + g + h * 8;
            if (i < NWIN) {
                int ci = code[i];
                #pragma unroll
                for (int ni = 0; ni < 4; ni++) {
                    int j0 = nb + ni * 8 + 2 * t4;
                    #pragma unroll
                    for (int e = 0; e < 2; e++) {
                        int j = j0 + e;
                        if (j < NWIN) {
                            int cj = code[j];
                            int rp = (ci & 0xffff) - (cj & 0xffff) + 84;
                            float mask = ((ci ^ cj) & 0xffff0000) ? -100.0f : 0.0f;
                            s[i][j] = acc[ni][2 * h + e] * ATT_SCALE + bias_s[rp] + mask;
                        }
                    }
                }
            }
        }
    }
    __syncthreads();

    // ---- softmax: warp per row ----
    int warp = tid >> 5, lane = tid & 31;
    for (int i = warp; i < NWIN; i += 8) {
        float m = -1e30f;
        for (int j = lane; j < NWIN; j += 32) m = fmaxf(m, s[i][j]);
        #pragma unroll
        for (int o = 16; o > 0; o >>= 1) m = fmaxf(m, __shfl_xor_sync(0xffffffff, m, o));
        float sum = 0.0f;
        for (int j = lane; j < NWIN; j += 32) { float e = __expf(s[i][j] - m); s[i][j] = e; sum += e; }
        #pragma unroll
        for (int o = 16; o > 0; o >>= 1) sum += __shfl_xor_sync(0xffffffff, sum, o);
        float inv = 1.0f / sum;
        for (int j = lane; j < NWIN; j += 32) s[i][j] *= inv;
    }
    __syncthreads();

    // ---- PV: warp per row i; lane owns column d; v word broadcast to lane pairs ----
    for (int i = warp; i < NWIN; i += 8) {
        float acc = 0.0f;
        int wsel = lane >> 1, hsel = lane & 1;
        #pragma unroll
        for (int j = 0; j < NWIN; j++) {
            float sv = s[i][j];
            __half2 vh = *reinterpret_cast<const __half2*>(&v[j][wsel]);
            float ve = hsel ? __high2float(vh) : __low2float(vh);
            acc += sv * ve;
        }
        out[((size_t)(w * NWIN + i)) * CC + head * HD + lane] = __float2half_rn(acc);
    }
}

// ---------------- launcher ----------------
extern "C" void kernel_launch(void* const* d_in, const int* in_sizes, int n_in,
                              void* d_out, int out_size)
{
    (void)in_sizes; (void)n_in; (void)out_size;
    const float* x        = (const float*)d_in[0];
    const float* qkv_w    = (const float*)d_in[1];
    const float* qkv_b    = (const float*)d_in[2];
    const float* proj_w   = (const float*)d_in[3];
    const float* proj_b   = (const float*)d_in[4];
    const float* rel_bias = (const float*)d_in[5];
    const float* ln1_g    = (const float*)d_in[6];
    const float* ln1_b    = (const float*)d_in[7];
    const float* ln2_g    = (const float*)d_in[8];
    const float* ln2_b    = (const float*)d_in[9];
    const float* mlp_w1   = (const float*)d_in[10];
    const float* mlp_b1   = (const float*)d_in[11];
    const float* mlp_w2   = (const float*)d_in[12];
    const float* mlp_b2   = (const float*)d_in[13];
    float* out = (float*)d_out;

    __half *xw, *xn2, *qkvb, *att, *hbuf, *wq, *wp, *w1, *w2;
    float *x1;
    cudaGetSymbolAddress((void**)&xw,   g_xw);
    cudaGetSymbolAddress((void**)&xn2,  g_xn2);
    cudaGetSymbolAddress((void**)&qkvb, g_qkv);
    cudaGetSymbolAddress((void**)&att,  g_att);
    cudaGetSymbolAddress((void**)&x1,   g_x1);
    cudaGetSymbolAddress((void**)&hbuf, g_h);
    cudaGetSymbolAddress((void**)&wq,   g_wq);
    cudaGetSymbolAddress((void**)&wp,   g_wp);
    cudaGetSymbolAddress((void**)&w1,   g_w1);
    cudaGetSymbolAddress((void**)&w2,   g_w2);

    const int SMEM3 = 3 * 2 * 128 * LDKH2 * 2;   // 110592 B (3-stage ring)
    cudaFuncSetAttribute(mma_gemm<0, 256,  768>, cudaFuncAttributeMaxDynamicSharedMemorySize, SMEM3);
    cudaFuncSetAttribute(mma_gemm<1, 256,  256>, cudaFuncAttributeMaxDynamicSharedMemorySize, SMEM3);
    cudaFuncSetAttribute(mma_gemm<2, 256, 1024>, cudaFuncAttributeMaxDynamicSharedMemorySize, SMEM3);
    cudaFuncSetAttribute(mma_gemm<3, 1024, 256>, cudaFuncAttributeMaxDynamicSharedMemorySize, SMEM3);

    // 1. LN1 + shift + window partition -> fp16 xw
    ln_apply_kernel<true><<<TOK / 8, 256>>>(x, ln1_g, ln1_b, xw);
    // 2. all weight transposes in one launch
    transpose_all_kernel<<<768, dim3(32, 8)>>>(qkv_w, proj_w, mlp_w1, mlp_w2, wq, wp, w1, w2);
    // 3. QKV GEMM (half out)
    mma_gemm<0, 256, 768><<<dim3(768 / 128, TOK / 128), 256, SMEM3>>>(xw, wq, qkv_b, qkvb, nullptr);
    // 4. windowed attention (half in/out)
    attn_kernel<<<dim3(NWTOT, HEADS), 256>>>(qkvb, rel_bias, att);
    // 5. proj GEMM + window reverse + roll + residual (float out)
    mma_gemm<1, 256, 256><<<dim3(256 / 128, TOK / 128), 256, SMEM3>>>(att, wp, proj_b, x1, x);
    // 6. LN2 -> fp16 xn2
    ln_apply_kernel<false><<<TOK / 8, 256>>>(x1, ln2_g, ln2_b, xn2);
    // 7. MLP1 + GELU (half out)
    mma_gemm<2, 256, 1024><<<dim3(1024 / 128, TOK / 128), 256, SMEM3>>>(xn2, w1, mlp_b1, hbuf, nullptr);
    // 8. MLP2 + residual -> d_out (float out)
    mma_gemm<3, 1024, 256><<<dim3(256 / 128, TOK / 128), 256, SMEM3>>>(hbuf, w2, mlp_b2, out, x1);
}

// round 16
// speedup vs baseline: 1.7609x; 1.1472x over previous
#include <cuda_runtime.h>
#include <cuda_fp16.h>
#include <math.h>
#include <cstdint>

// ---------------- problem constants ----------------
#define TOK    100352          // 32 * 56 * 56 tokens
#define CC     256
#define HEADS  8
#define HD     32
#define WS     7
#define NWIN   49
#define MLPD   1024
#define HH     56
#define WW     56
#define SSH    3
#define NWB    64
#define NWTOT  2048
#define ATT_SCALE 0.17677669529663687f
#define LN_EPS 1e-5f

// ---------------- scratch (static device globals; no allocation) ----------------
__device__ __half g_xw  [(size_t)TOK * CC];
__device__ __half g_xn2 [(size_t)TOK * CC];
__device__ __half g_qkv [(size_t)TOK * 3 * CC];
__device__ __half g_att [(size_t)TOK * CC];
__device__ float  g_x1  [(size_t)TOK * CC];
__device__ __half g_h   [(size_t)TOK * MLPD];
// transposed weights [N,K] row-major, fp16
__device__ __half g_wq [768 * 256];
__device__ __half g_wp [256 * 256];
__device__ __half g_w1 [1024 * 256];
__device__ __half g_w2 [256 * 1024];

// ---------------- helpers ----------------
__device__ __forceinline__ uint32_t smem_u32(const void* p) {
    uint32_t a;
    asm("{ .reg .u64 t; cvta.to.shared.u64 t, %1; cvt.u32.u64 %0, t; }" : "=r"(a) : "l"(p));
    return a;
}
__device__ __forceinline__ void cp_async16(uint32_t dst, const void* src) {
    asm volatile("cp.async.cg.shared.global [%0], [%1], 16;" :: "r"(dst), "l"(src));
}
#define CP_COMMIT() asm volatile("cp.async.commit_group;" ::: "memory")

// m16n8k16 fp16 MMA, fp32 accumulate
__device__ __forceinline__ void mma_f16(float* c,
                                        uint32_t a0, uint32_t a1, uint32_t a2, uint32_t a3,
                                        uint32_t b0, uint32_t b1) {
    asm volatile(
        "mma.sync.aligned.m16n8k16.row.col.f32.f16.f16.f32 "
        "{%0,%1,%2,%3}, {%4,%5,%6,%7}, {%8,%9}, {%0,%1,%2,%3};"
        : "+f"(c[0]), "+f"(c[1]), "+f"(c[2]), "+f"(c[3])
        : "r"(a0), "r"(a1), "r"(a2), "r"(a3), "r"(b0), "r"(b1));
}
__device__ __forceinline__ void ldsm_x4(uint32_t addr, uint32_t& r0, uint32_t& r1,
                                        uint32_t& r2, uint32_t& r3) {
    asm volatile("ldmatrix.sync.aligned.m8n8.x4.shared.b16 {%0,%1,%2,%3}, [%4];"
                 : "=r"(r0), "=r"(r1), "=r"(r2), "=r"(r3) : "r"(addr));
}

#define LDKH2 72   // padded row stride (halves) for 64-half chunks

// scalar-LDS K-step MMA over 64-half chunk (proven form)
__device__ __forceinline__ void chunk_mma64(const __half* As, const __half* Bs,
                                            int wm, int wn, int g, int t4,
                                            float acc[4][4][4]) {
    #pragma unroll
    for (int ks = 0; ks < 4; ks++) {
        const int kb = ks * 16;
        uint32_t bf[4][2];
        #pragma unroll
        for (int ni = 0; ni < 4; ni++) {
            const __half* bp = Bs + (wn + ni * 8 + g) * LDKH2 + kb + t4 * 2;
            bf[ni][0] = *reinterpret_cast<const uint32_t*>(bp);
            bf[ni][1] = *reinterpret_cast<const uint32_t*>(bp + 8);
        }
        #pragma unroll
        for (int mi = 0; mi < 4; mi++) {
            const __half* ap = As + (wm + mi * 16 + g) * LDKH2 + kb + t4 * 2;
            uint32_t a0 = *reinterpret_cast<const uint32_t*>(ap);
            uint32_t a1 = *reinterpret_cast<const uint32_t*>(ap + 8 * LDKH2);
            uint32_t a2 = *reinterpret_cast<const uint32_t*>(ap + 8);
            uint32_t a3 = *reinterpret_cast<const uint32_t*>(ap + 8 * LDKH2 + 8);
            #pragma unroll
            for (int ni = 0; ni < 4; ni++)
                mma_f16(acc[mi][ni], a0, a1, a2, a3, bf[ni][0], bf[ni][1]);
        }
    }
}

// shared epilogue. MODE 0: half out (QKV)  MODE 1: float res+scatter (proj)
// MODE 2: half gelu out (MLP1)  MODE 3: float res out (MLP2)
template<int MODE, int NDIM>
__device__ __forceinline__ void gemm_epilogue(float acc[4][4][4],
                                              int m0, int n0, int wm, int wn, int g, int t4,
                                              const float* __restrict__ bias,
                                              void* __restrict__ OutV,
                                              const float* __restrict__ res) {
    #pragma unroll
    for (int mi = 0; mi < 4; mi++) {
        #pragma unroll
        for (int h = 0; h < 2; h++) {
            int m = m0 + wm + mi * 16 + g + h * 8;
            size_t drow;
            if (MODE == 1) {
                int w = m / NWIN, ntok = m % NWIN;
                int bb2 = w / NWB, wi = w % NWB;
                int wy = wi >> 3, wx = wi & 7;
                int hy = wy * WS + ntok / WS, hx = wx * WS + ntok % WS;
                int oy = (hy + SSH) % HH, ox = (hx + SSH) % WW;
                drow = ((size_t)bb2 * HH * WW + oy * WW + ox) * CC;
            } else {
                drow = (size_t)m * NDIM;
            }
            #pragma unroll
            for (int ni = 0; ni < 4; ni++) {
                int n = n0 + wn + ni * 8 + 2 * t4;
                float2 bv = *reinterpret_cast<const float2*>(bias + n);
                float vx = acc[mi][ni][2 * h + 0] + bv.x;
                float vy = acc[mi][ni][2 * h + 1] + bv.y;
                if (MODE == 1 || MODE == 3) {
                    float2 r = *reinterpret_cast<const float2*>(res + drow + n);
                    float2 o = { vx + r.x, vy + r.y };
                    *reinterpret_cast<float2*>((float*)OutV + drow + n) = o;
                } else {
                    if (MODE == 2) {
                        vx = 0.5f * vx * (1.0f + erff(vx * 0.70710678118654752f));
                        vy = 0.5f * vy * (1.0f + erff(vy * 0.70710678118654752f));
                    }
                    *reinterpret_cast<__half2*>((__half*)OutV + drow + n) =
                        __floats2half2_rn(vx, vy);
                }
            }
        }
    }
}

// ---------------- cp.async fp16 GEMM, 64-half K chunks, 3-stage ring ----------------
template<int MODE, int KDIM, int NDIM>
__global__ __launch_bounds__(256)
void mma_gemm(const __half* __restrict__ A, const __half* __restrict__ Wt,
              const float* __restrict__ bias, void* __restrict__ Out,
              const float* __restrict__ res)
{
    extern __shared__ char smraw[];
    __half* sm = reinterpret_cast<__half*>(smraw);
    const uint32_t sbase = smem_u32(smraw);

    const int tid  = threadIdx.x;
    const int wid  = tid >> 5, lane = tid & 31;
    const int g    = lane >> 2, t4 = lane & 3;
    const int wm   = (wid & 1) * 64;
    const int wn   = (wid >> 1) * 32;
    const int m0   = blockIdx.y * 128;
    const int n0   = blockIdx.x * 128;

    constexpr int NC = KDIM / 64;
    constexpr int STAGE = 2 * 128 * LDKH2;

    auto load_chunk = [&](int c, int s) {
        const int k0 = c * 64;
        uint32_t sa  = sbase + (uint32_t)(s * STAGE) * 2u;
        uint32_t sb2 = sa + 128u * LDKH2 * 2u;
        #pragma unroll
        for (int t = 0; t < 4; t++) {
            int f = t * 256 + tid;
            int row = f >> 3, seg = f & 7;
            cp_async16(sa  + (uint32_t)(row * LDKH2) * 2u + seg * 16,
                       A  + (size_t)(m0 + row) * KDIM + k0 + seg * 8);
            cp_async16(sb2 + (uint32_t)(row * LDKH2) * 2u + seg * 16,
                       Wt + (size_t)(n0 + row) * KDIM + k0 + seg * 8);
        }
        CP_COMMIT();
    };

    float acc[4][4][4];
    #pragma unroll
    for (int i = 0; i < 4; i++)
        #pragma unroll
        for (int j = 0; j < 4; j++)
            #pragma unroll
            for (int e = 0; e < 4; e++) acc[i][j][e] = 0.0f;

    load_chunk(0, 0);
    load_chunk(1, 1);

    int stage = 0;
    for (int c = 0; c < NC; c++) {
        if (c + 1 < NC) asm volatile("cp.async.wait_group 1;" ::: "memory");
        else            asm volatile("cp.async.wait_group 0;" ::: "memory");
        __syncthreads();
        if (c + 2 < NC) {
            int s2 = stage + 2; if (s2 >= 3) s2 -= 3;
            load_chunk(c + 2, s2);
        }
        const __half* As = sm + stage * STAGE;
        const __half* Bs = As + 128 * LDKH2;
        chunk_mma64(As, Bs, wm, wn, g, t4, acc);
        if (++stage == 3) stage = 0;
    }
    gemm_epilogue<MODE, NDIM>(acc, m0, n0, wm, wn, g, t4, bias, Out, res);
}

// ---------------- fused LN apply: warp/token, stats + normalize -> fp16 ----------------
template<bool SHIFT>
__global__ __launch_bounds__(256)
void ln_apply_kernel(const float* __restrict__ x,
                     const float* __restrict__ g,
                     const float* __restrict__ b,
                     __half* __restrict__ out)
{
    int t = blockIdx.x * 8 + (threadIdx.x >> 5);
    int lane = threadIdx.x & 31;

    int src;
    if (SHIFT) {
        int w = t / NWIN, n = t % NWIN;
        int bb = w >> 6, wi = w & 63;
        int wy = wi >> 3, wx = wi & 7;
        int hy = wy * WS + n / WS, hx = wx * WS + n % WS;
        int sy = hy + SSH; if (sy >= HH) sy -= HH;
        int sx = hx + SSH; if (sx >= WW) sx -= WW;
        src = bb * (HH * WW) + sy * WW + sx;
    } else {
        src = t;
    }

    const float4* rp = reinterpret_cast<const float4*>(x + (size_t)src * CC);
    float4 a = rp[lane], c = rp[lane + 32];
    float s  = a.x + a.y + a.z + a.w + c.x + c.y + c.z + c.w;
    float s2 = a.x * a.x + a.y * a.y + a.z * a.z + a.w * a.w
             + c.x * c.x + c.y * c.y + c.z * c.z + c.w * c.w;
    #pragma unroll
    for (int o = 16; o > 0; o >>= 1) {
        s  += __shfl_xor_sync(0xffffffff, s, o);
        s2 += __shfl_xor_sync(0xffffffff, s2, o);
    }
    float mu  = s * (1.0f / CC);
    float var = s2 * (1.0f / CC) - mu * mu;
    float inv = rsqrtf(var + LN_EPS);

    const float4* gp = reinterpret_cast<const float4*>(g);
    const float4* bp = reinterpret_cast<const float4*>(b);
    uint2* op = reinterpret_cast<uint2*>(out + (size_t)t * CC);
    #pragma unroll
    for (int h = 0; h < 2; h++) {
        float4 v = h ? c : a;
        float4 gg = gp[lane + h * 32], bb4 = bp[lane + h * 32];
        __half2 h01 = __floats2half2_rn((v.x - mu) * inv * gg.x + bb4.x,
                                        (v.y - mu) * inv * gg.y + bb4.y);
        __half2 h23 = __floats2half2_rn((v.z - mu) * inv * gg.z + bb4.z,
                                        (v.w - mu) * inv * gg.w + bb4.w);
        uint2 pk = { *reinterpret_cast<uint32_t*>(&h01), *reinterpret_cast<uint32_t*>(&h23) };
        op[lane + h * 32] = pk;
    }
}

// ---------------- merged weight transpose (all 4 weights in one launch) ----------------
__global__ void transpose_all_kernel(const float* __restrict__ qkv_w,
                                     const float* __restrict__ proj_w,
                                     const float* __restrict__ mlp_w1,
                                     const float* __restrict__ mlp_w2,
                                     __half* __restrict__ wq, __half* __restrict__ wp,
                                     __half* __restrict__ w1, __half* __restrict__ w2)
{
    __shared__ float t[32][33];
    int bidx = blockIdx.x;
    const float* W; __half* Wt; int K, N, tile;
    if (bidx < 192)      { W = qkv_w;  Wt = wq; K = 256;  N = 768;  tile = bidx; }
    else if (bidx < 256) { W = proj_w; Wt = wp; K = 256;  N = 256;  tile = bidx - 192; }
    else if (bidx < 512) { W = mlp_w1; Wt = w1; K = 256;  N = 1024; tile = bidx - 256; }
    else                 { W = mlp_w2; Wt = w2; K = 1024; N = 256;  tile = bidx - 512; }
    int ntx = N >> 5;
    int by = tile / ntx, bx = tile - by * ntx;
    int k0 = by * 32, n0 = bx * 32;
    int tx = threadIdx.x, ty = threadIdx.y;   // 32 x 8
    for (int i = ty; i < 32; i += 8) t[i][tx] = W[(size_t)(k0 + i) * N + n0 + tx];
    __syncthreads();
    for (int i = ty; i < 32; i += 8) Wt[(size_t)(n0 + i) * K + k0 + tx] = __float2half_rn(t[tx][i]);
}

// ---------------- windowed attention: HMMA score + HMMA PV (split-precision P) ----------------
#define LDQ  40   // halves per q/k row (20 words)
#define LDP  72   // halves per p row (64 data + 8 pad)
#define LDV  72   // halves per vT row
__global__ __launch_bounds__(256)
void attn_kernel(const __half* __restrict__ qkv,
                 const float* __restrict__ rel_bias,
                 __half* __restrict__ out)
{
    int w    = blockIdx.x;
    int head = blockIdx.y;
    int tid  = threadIdx.x;

    __shared__ __half qs[64 * LDQ];      // rows 49..63 garbage (guarded)
    __shared__ __half ksm[64 * LDQ];
    __shared__ __half p[64 * LDP];       // fp16 hi part of probabilities (padded cols zero)
    __shared__ __half plo[64 * LDP];     // fp16 residual (p - hi)
    __shared__ __half vT[32 * LDV];      // V transposed [d][j], cols >=49 zeroed
    __shared__ float s[NWIN][52];
    __shared__ float bias_s[169];
    __shared__ int   code[NWIN];

    for (int i = tid; i < 169; i += 256)
        bias_s[i] = rel_bias[i * HEADS + head];

    if (tid < NWIN) {
        int wi = w % NWB;
        int wy = wi >> 3, wx = wi & 7;
        int yi = tid / WS, xi = tid % WS;
        int gy = wy * WS + yi, gx = wx * WS + xi;
        int r = (gy < HH - WS ? 0 : (gy < HH - SSH ? 1 : 2)) * 3
              + (gx < WW - WS ? 0 : (gx < WW - SSH ? 1 : 2));
        code[tid] = (yi * 13 + xi) | (r << 16);
    }

    // zero vT (padded columns contribute exactly 0 in PV MMA)
    for (int i = tid; i < 32 * LDV / 2; i += 256)
        reinterpret_cast<uint32_t*>(vT)[i] = 0u;
    __syncthreads();   // *** zero-init fully visible before V scatter (race fix) ***

    // load q/k rows as raw half2 words; scatter v transposed
    for (int idx = tid; idx < NWIN * 16; idx += 256) {
        int n = idx >> 4, wd = idx & 15;
        size_t base = ((size_t)(w * NWIN + n)) * (3 * CC) + head * HD + wd * 2;
        *reinterpret_cast<uint32_t*>(&qs[n * LDQ + wd * 2])  = *reinterpret_cast<const uint32_t*>(qkv + base);
        *reinterpret_cast<uint32_t*>(&ksm[n * LDQ + wd * 2]) = *reinterpret_cast<const uint32_t*>(qkv + base + CC);
        __half2 vh = *reinterpret_cast<const __half2*>(qkv + base + 2 * CC);
        vT[(wd * 2 + 0) * LDV + n] = __low2half(vh);
        vT[(wd * 2 + 1) * LDV + n] = __high2half(vh);
    }
    __syncthreads();

    const int wid = tid >> 5, lane = tid & 31;
    const int g = lane >> 2, t4 = lane & 3;
    const int lr = lane & 7, lt8 = (lane >> 3) & 1, lt16 = lane >> 4;

    // ---- score via HMMA: 64x64x32, 8 warps x (16m x 32n) ----
    {
        const int mi = (wid & 3) * 16;
        const int nb = (wid >> 2) * 32;
        const uint32_t qbase = smem_u32(qs);
        const uint32_t kbase = smem_u32(ksm);

        float acc[4][4];
        #pragma unroll
        for (int a = 0; a < 4; a++)
            #pragma unroll
            for (int e = 0; e < 4; e++) acc[a][e] = 0.0f;

        #pragma unroll
        for (int kstep = 0; kstep < 2; kstep++) {
            const int kb = kstep * 16;
            uint32_t bf[4][2];
            #pragma unroll
            for (int np = 0; np < 2; np++) {
                uint32_t addr = kbase + (uint32_t)(((nb + np * 16 + lt16 * 8 + lr) * LDQ
                                                    + kb + lt8 * 8) * 2);
                ldsm_x4(addr, bf[2 * np][0], bf[2 * np][1], bf[2 * np + 1][0], bf[2 * np + 1][1]);
            }
            uint32_t aaddr = qbase + (uint32_t)(((mi + lt8 * 8 + lr) * LDQ + kb + lt16 * 8) * 2);
            uint32_t a0, a1, a2, a3;
            ldsm_x4(aaddr, a0, a1, a2, a3);
            #pragma unroll
            for (int ni = 0; ni < 4; ni++)
                mma_f16(acc[ni], a0, a1, a2, a3, bf[ni][0], bf[ni][1]);
        }

        #pragma unroll
        for (int h = 0; h < 2; h++) {
            int i = mi + g + h * 8;
            if (i < NWIN) {
                int ci = code[i];
                #pragma unroll
                for (int ni = 0; ni < 4; ni++) {
                    int j0 = nb + ni * 8 + 2 * t4;
                    #pragma unroll
                    for (int e = 0; e < 2; e++) {
                        int j = j0 + e;
                        if (j < NWIN) {
                            int cj = code[j];
                            int rp = (ci & 0xffff) - (cj & 0xffff) + 84;
                            float mask = ((ci ^ cj) & 0xffff0000) ? -100.0f : 0.0f;
                            s[i][j] = acc[ni][2 * h + e] * ATT_SCALE + bias_s[rp] + mask;
                        }
                    }
                }
            }
        }
    }
    __syncthreads();

    // ---- softmax (warp per row) + split-precision fp16 pack (zero-padded) ----
    for (int i = wid; i < NWIN; i += 8) {
        float m = -1e30f;
        for (int j = lane; j < NWIN; j += 32) m = fmaxf(m, s[i][j]);
        #pragma unroll
        for (int o = 16; o > 0; o >>= 1) m = fmaxf(m, __shfl_xor_sync(0xffffffff, m, o));
        float sum = 0.0f;
        for (int j = lane; j < NWIN; j += 32) { float e = __expf(s[i][j] - m); s[i][j] = e; sum += e; }
        #pragma unroll
        for (int o = 16; o > 0; o >>= 1) sum += __shfl_xor_sync(0xffffffff, sum, o);
        float inv = 1.0f / sum;
        int j0 = 2 * lane;
        float p0 = (j0 < NWIN)     ? s[i][j0] * inv     : 0.0f;
        float p1 = (j0 + 1 < NWIN) ? s[i][j0 + 1] * inv : 0.0f;
        __half h0 = __float2half_rn(p0), h1 = __float2half_rn(p1);
        __half l0 = __float2half_rn(p0 - __half2float(h0));
        __half l1 = __float2half_rn(p1 - __half2float(h1));
        *reinterpret_cast<__half2*>(&p[i * LDP + j0])   = __halves2half2(h0, h1);
        *reinterpret_cast<__half2*>(&plo[i * LDP + j0]) = __halves2half2(l0, l1);
    }
    __syncthreads();

    // ---- PV via HMMA: out = (p_hi + p_lo) @ vT^T; warps 0-3, 16m x 32n each ----
    if (wid < 4) {
        const int mi = wid * 16;
        const uint32_t pbase  = smem_u32(p);
        const uint32_t plbase = smem_u32(plo);
        const uint32_t vbase  = smem_u32(vT);

        float acc[4][4];
        #pragma unroll
        for (int a = 0; a < 4; a++)
            #pragma unroll
            for (int e = 0; e < 4; e++) acc[a][e] = 0.0f;

        #pragma unroll
        for (int kstep = 0; kstep < 4; kstep++) {
            const int kb = kstep * 16;
            uint32_t bf[4][2];
            #pragma unroll
            for (int np = 0; np < 2; np++) {
                uint32_t addr = vbase + (uint32_t)(((np * 16 + lt16 * 8 + lr) * LDV
                                                    + kb + lt8 * 8) * 2);
                ldsm_x4(addr, bf[2 * np][0], bf[2 * np][1], bf[2 * np + 1][0], bf[2 * np + 1][1]);
            }
            const uint32_t roff = (uint32_t)(((mi + lt8 * 8 + lr) * LDP + kb + lt16 * 8) * 2);
            uint32_t a0, a1, a2, a3;
            ldsm_x4(pbase + roff, a0, a1, a2, a3);
            #pragma unroll
            for (int ni = 0; ni < 4; ni++)
                mma_f16(acc[ni], a0, a1, a2, a3, bf[ni][0], bf[ni][1]);
            ldsm_x4(plbase + roff, a0, a1, a2, a3);
            #pragma unroll
            for (int ni = 0; ni < 4; ni++)
                mma_f16(acc[ni], a0, a1, a2, a3, bf[ni][0], bf[ni][1]);
        }

        #pragma unroll
        for (int h = 0; h < 2; h++) {
            int i = mi + g + h * 8;
            if (i < NWIN) {
                size_t orow = ((size_t)(w * NWIN + i)) * CC + head * HD;
                #pragma unroll
                for (int ni = 0; ni < 4; ni++) {
                    int d = ni * 8 + 2 * t4;
                    *reinterpret_cast<__half2*>(out + orow + d) =
                        __floats2half2_rn(acc[ni][2 * h + 0], acc[ni][2 * h + 1]);
                }
            }
        }
    }
}

// ---------------- launcher ----------------
extern "C" void kernel_launch(void* const* d_in, const int* in_sizes, int n_in,
                              void* d_out, int out_size)
{
    (void)in_sizes; (void)n_in; (void)out_size;
    const float* x        = (const float*)d_in[0];
    const float* qkv_w    = (const float*)d_in[1];
    const float* qkv_b    = (const float*)d_in[2];
    const float* proj_w   = (const float*)d_in[3];
    const float* proj_b   = (const float*)d_in[4];
    const float* rel_bias = (const float*)d_in[5];
    const float* ln1_g    = (const float*)d_in[6];
    const float* ln1_b    = (const float*)d_in[7];
    const float* ln2_g    = (const float*)d_in[8];
    const float* ln2_b    = (const float*)d_in[9];
    const float* mlp_w1   = (const float*)d_in[10];
    const float* mlp_b1   = (const float*)d_in[11];
    const float* mlp_w2   = (const float*)d_in[12];
    const float* mlp_b2   = (const float*)d_in[13];
    float* out = (float*)d_out;

    __half *xw, *xn2, *qkvb, *att, *hbuf, *wq, *wp, *w1, *w2;
    float *x1;
    cudaGetSymbolAddress((void**)&xw,   g_xw);
    cudaGetSymbolAddress((void**)&xn2,  g_xn2);
    cudaGetSymbolAddress((void**)&qkvb, g_qkv);
    cudaGetSymbolAddress((void**)&att,  g_att);
    cudaGetSymbolAddress((void**)&x1,   g_x1);
    cudaGetSymbolAddress((void**)&hbuf, g_h);
    cudaGetSymbolAddress((void**)&wq,   g_wq);
    cudaGetSymbolAddress((void**)&wp,   g_wp);
    cudaGetSymbolAddress((void**)&w1,   g_w1);
    cudaGetSymbolAddress((void**)&w2,   g_w2);

    const int SMEM3 = 3 * 2 * 128 * LDKH2 * 2;   // 110592 B (3-stage ring)
    cudaFuncSetAttribute(mma_gemm<0, 256,  768>, cudaFuncAttributeMaxDynamicSharedMemorySize, SMEM3);
    cudaFuncSetAttribute(mma_gemm<1, 256,  256>, cudaFuncAttributeMaxDynamicSharedMemorySize, SMEM3);
    cudaFuncSetAttribute(mma_gemm<2, 256, 1024>, cudaFuncAttributeMaxDynamicSharedMemorySize, SMEM3);
    cudaFuncSetAttribute(mma_gemm<3, 1024, 256>, cudaFuncAttributeMaxDynamicSharedMemorySize, SMEM3);

    // 1. LN1 + shift + window partition -> fp16 xw
    ln_apply_kernel<true><<<TOK / 8, 256>>>(x, ln1_g, ln1_b, xw);
    // 2. all weight transposes in one launch
    transpose_all_kernel<<<768, dim3(32, 8)>>>(qkv_w, proj_w, mlp_w1, mlp_w2, wq, wp, w1, w2);
    // 3. QKV GEMM (half out)
    mma_gemm<0, 256, 768><<<dim3(768 / 128, TOK / 128), 256, SMEM3>>>(xw, wq, qkv_b, qkvb, nullptr);
    // 4. windowed attention (half in/out)
    attn_kernel<<<dim3(NWTOT, HEADS), 256>>>(qkvb, rel_bias, att);
    // 5. proj GEMM + window reverse + roll + residual (float out)
    mma_gemm<1, 256, 256><<<dim3(256 / 128, TOK / 128), 256, SMEM3>>>(att, wp, proj_b, x1, x);
    // 6. LN2 -> fp16 xn2
    ln_apply_kernel<false><<<TOK / 8, 256>>>(x1, ln2_g, ln2_b, xn2);
    // 7. MLP1 + GELU (half out)
    mma_gemm<2, 256, 1024><<<dim3(1024 / 128, TOK / 128), 256, SMEM3>>>(xn2, w1, mlp_b1, hbuf, nullptr);
    // 8. MLP2 + residual -> d_out (float out)
    mma_gemm<3, 1024, 256><<<dim3(256 / 128, TOK / 128), 256, SMEM3>>>(hbuf, w2, mlp_b2, out, x1);
}